// round 8
// baseline (speedup 1.0000x reference)
#include <cuda_runtime.h>
#include <cuda_bf16.h>
#include <cstdint>
#include <math.h>

#define BB 4
#define NN 1024
#define PP 42
#define DD 96
#define PD 4032          // PP*DD
#define KNODE 8
#define KCAND 12         // prepass candidates (margin over 8)
#define KTOK 8
#define KTC 12           // token prepass candidates
#define POUT 50          // PP + KTOK
#define EPSD 1e-7

#define NEG_INF __int_as_float(0xff800000)
#define NEG_INF_D (-1.0e300)

// ---------------- scratch (device globals; no allocation) ----------------
__device__ float  g_sim[BB * NN * NN];
__device__ __align__(16) __nv_bfloat16 g_hbf[BB * NN * PD];
__device__ double g_inv_node_d[BB * NN];
__device__ float  g_inv_node_f[BB * NN];
__device__ double g_inv_tok_d[BB * NN * PP];
__device__ int    g_cand[BB * NN * KCAND];
__device__ int    g_sel[BB * NN * KTOK];      // selected tokens: m*64 + p

// ---------------- compensated arithmetic helpers --------------------------
__device__ __forceinline__ void two_sum(float a, float b, float& s, float& e) {
    s = a + b;
    float z = s - a;
    e = (a - (s - z)) + (b - z);
}
__device__ __forceinline__ void dot2_step(float a, float b, float& hi, float& lo) {
    float p = a * b;
    float ep = fmaf(a, b, -p);
    float s, e;
    two_sum(hi, p, s, e);
    hi = s;
    lo += e + ep;
}

__device__ __forceinline__ void cp16(uint32_t s, const void* g) {
    asm volatile("cp.async.cg.shared.global [%0], [%1], 16;\n" :: "r"(s), "l"(g));
}

// ---------------- packed f32x2 helpers (Blackwell FFMA2) ------------------
__device__ __forceinline__ unsigned long long pk2(float lo, float hi) {
    unsigned long long r;
    asm("mov.b64 %0, {%1, %2};" : "=l"(r) : "f"(lo), "f"(hi));
    return r;
}
__device__ __forceinline__ void fma2(unsigned long long& d,
                                     unsigned long long a, unsigned long long b) {
    asm("fma.rn.f32x2 %0, %1, %2, %0;" : "+l"(d) : "l"(a), "l"(b));
}
__device__ __forceinline__ void upk2(unsigned long long v, float& lo, float& hi) {
    asm("mov.b64 {%0, %1}, %2;" : "=f"(lo), "=f"(hi) : "l"(v));
}

// =========================================================================
// K1: FUSED bf16 conversion + exact token/node norms.
// =========================================================================
__global__ __launch_bounds__(128) void k_convnorm(const float* __restrict__ h) {
    int bn = blockIdx.x;
    const float* base = h + (size_t)bn * PD;
    __shared__ double s_node[4];
    int t = threadIdx.x, warp = t >> 5, lane = t & 31;

    const float4* b4 = (const float4*)base;
    uint2* o2 = (uint2*)(g_hbf + (size_t)bn * PD);
    for (int i = t; i < PD / 4; i += 128) {
        float4 v = b4[i];
        __nv_bfloat162 lo = __floats2bfloat162_rn(v.x, v.y);
        __nv_bfloat162 hi = __floats2bfloat162_rn(v.z, v.w);
        uint2 pkv;
        pkv.x = *(uint32_t*)&lo;
        pkv.y = *(uint32_t*)&hi;
        o2[i] = pkv;
    }

    double nodesum = 0.0;
    for (int p = warp; p < PP; p += 4) {
        const float* tp = base + p * DD;
        float hi = 0.f, lo = 0.f;
        float v0 = tp[lane], v1 = tp[lane + 32], v2 = tp[lane + 64];
        dot2_step(v0, v0, hi, lo);
        dot2_step(v1, v1, hi, lo);
        dot2_step(v2, v2, hi, lo);
        double s = (double)hi + (double)lo;
        #pragma unroll
        for (int o = 16; o; o >>= 1) s += __shfl_xor_sync(0xffffffffu, s, o);
        if (lane == 0) g_inv_tok_d[bn * PP + p] = 1.0 / (sqrt(s) + EPSD);
        nodesum += s;
    }
    if (lane == 0) s_node[warp] = nodesum;
    __syncthreads();
    if (t == 0) {
        double tt = s_node[0] + s_node[1] + s_node[2] + s_node[3];
        double inv = 1.0 / (sqrt(tt) + EPSD);
        g_inv_node_d[bn] = inv;
        g_inv_node_f[bn] = (float)inv;
    }
}

// =========================================================================
// K2: bf16 tensor-core prepass GEMM (symmetric, upper tiles + mirror).
// =========================================================================
__global__ void __launch_bounds__(256, 2) k_sim_mma() {
    if (blockIdx.y > blockIdx.x) return;
    extern __shared__ __align__(16) unsigned char smraw[];
    const int t = threadIdx.x;
    const int lane = t & 31, warp = t >> 5;
    const int warp_m = warp >> 2, warp_n = warp & 3;
    const int bz = blockIdx.z;
    const int rowBase = blockIdx.y * 128, colBase = blockIdx.x * 128;
    const __nv_bfloat16* base = g_hbf + (size_t)bz * NN * PD;
    uint32_t s0 = (uint32_t)__cvta_generic_to_shared(smraw);

    float acc[4][4][4];
    #pragma unroll
    for (int i = 0; i < 4; i++)
        #pragma unroll
        for (int j = 0; j < 4; j++)
            #pragma unroll
            for (int q = 0; q < 4; q++) acc[i][j][q] = 0.f;

    auto issue = [&](int it, int buf) {
        int k0 = it * 64;
        uint32_t sbuf = s0 + buf * 32768;
        #pragma unroll
        for (int i = 0; i < 4; i++) {
            int u = t + 256 * i;
            int r = u >> 3, c = u & 7;
            uint32_t soff = r * 128 + ((c ^ (r & 7)) << 4);
            cp16(sbuf + soff, base + (size_t)(rowBase + r) * PD + k0 + c * 8);
            cp16(sbuf + 16384 + soff, base + (size_t)(colBase + r) * PD + k0 + c * 8);
        }
        asm volatile("cp.async.commit_group;\n");
    };

    issue(0, 0);
    for (int it = 0; it < 63; it++) {
        if (it < 62) {
            issue(it + 1, (it + 1) & 1);
            asm volatile("cp.async.wait_group 1;\n");
        } else {
            asm volatile("cp.async.wait_group 0;\n");
        }
        __syncthreads();
        uint32_t sA = s0 + (it & 1) * 32768;
        uint32_t sB = sA + 16384;
        #pragma unroll
        for (int kk = 0; kk < 4; kk++) {
            uint32_t a[4][4], bf[4][2];
            #pragma unroll
            for (int mi = 0; mi < 4; mi++) {
                int row = warp_m * 64 + mi * 16 + ((lane >> 3) & 1) * 8 + (lane & 7);
                int ch = kk * 2 + (lane >> 4);
                uint32_t addr = sA + row * 128 + ((ch ^ (row & 7)) << 4);
                asm volatile("ldmatrix.sync.aligned.m8n8.x4.shared.b16 {%0,%1,%2,%3}, [%4];\n"
                    : "=r"(a[mi][0]), "=r"(a[mi][1]), "=r"(a[mi][2]), "=r"(a[mi][3]) : "r"(addr));
            }
            #pragma unroll
            for (int call = 0; call < 2; call++) {
                int row = warp_n * 32 + call * 16 + ((lane >> 4) & 1) * 8 + (lane & 7);
                int ch = kk * 2 + ((lane >> 3) & 1);
                uint32_t addr = sB + row * 128 + ((ch ^ (row & 7)) << 4);
                uint32_t r0, r1, r2, r3;
                asm volatile("ldmatrix.sync.aligned.m8n8.x4.shared.b16 {%0,%1,%2,%3}, [%4];\n"
                    : "=r"(r0), "=r"(r1), "=r"(r2), "=r"(r3) : "r"(addr));
                bf[call * 2][0] = r0; bf[call * 2][1] = r1;
                bf[call * 2 + 1][0] = r2; bf[call * 2 + 1][1] = r3;
            }
            #pragma unroll
            for (int mi = 0; mi < 4; mi++)
                #pragma unroll
                for (int ni = 0; ni < 4; ni++)
                    asm volatile("mma.sync.aligned.m16n8k16.row.col.f32.bf16.bf16.f32 "
                        "{%0,%1,%2,%3}, {%4,%5,%6,%7}, {%8,%9}, {%0,%1,%2,%3};\n"
                        : "+f"(acc[mi][ni][0]), "+f"(acc[mi][ni][1]),
                          "+f"(acc[mi][ni][2]), "+f"(acc[mi][ni][3])
                        : "r"(a[mi][0]), "r"(a[mi][1]), "r"(a[mi][2]), "r"(a[mi][3]),
                          "r"(bf[ni][0]), "r"(bf[ni][1]));
        }
        __syncthreads();
    }

    float* C = g_sim + (size_t)bz * NN * NN;
    const bool offdiag = (rowBase != colBase);
    #pragma unroll
    for (int mi = 0; mi < 4; mi++) {
        int r = rowBase + warp_m * 64 + mi * 16 + (lane >> 2);
        #pragma unroll
        for (int ni = 0; ni < 4; ni++) {
            int c = colBase + warp_n * 32 + ni * 8 + (lane & 3) * 2;
            *(float2*)(C + (size_t)r * NN + c) = make_float2(acc[mi][ni][0], acc[mi][ni][1]);
            *(float2*)(C + (size_t)(r + 8) * NN + c) = make_float2(acc[mi][ni][2], acc[mi][ni][3]);
            if (offdiag) {
                C[(size_t)c * NN + r]           = acc[mi][ni][0];
                C[(size_t)(c + 1) * NN + r]     = acc[mi][ni][1];
                C[(size_t)c * NN + r + 8]       = acc[mi][ni][2];
                C[(size_t)(c + 1) * NN + r + 8] = acc[mi][ni][3];
            }
        }
    }
}

// =========================================================================
// K3: prepass — normalize row, zero diag, select top-12 candidates.
// =========================================================================
__global__ __launch_bounds__(256) void k_topk_node() {
    int bn = blockIdx.x;
    int b = bn >> 10, n = bn & 1023;
    __shared__ float vals[NN];
    __shared__ float rv[256];
    __shared__ int   ri[256];
    int t = threadIdx.x;
    float invn = g_inv_node_f[bn];
    const float* row = g_sim + (size_t)b * NN * NN + (size_t)n * NN;
    for (int m = t; m < NN; m += 256) {
        vals[m] = (m == n) ? 0.f : row[m] * invn * g_inv_node_f[b * NN + m];
    }
    __syncthreads();
    for (int k = 0; k < KCAND; k++) {
        float bv = NEG_INF; int bi = 0;
        #pragma unroll
        for (int j = 0; j < 4; j++) {
            int m = t + j * 256;
            float v = vals[m];
            if (v > bv) { bv = v; bi = m; }
        }
        rv[t] = bv; ri[t] = bi;
        __syncthreads();
        if (t < 32) {
            float v = rv[t]; int i = ri[t];
            #pragma unroll
            for (int j = 1; j < 8; j++) {
                float v2 = rv[t + j * 32]; int i2 = ri[t + j * 32];
                if (v2 > v || (v2 == v && i2 < i)) { v = v2; i = i2; }
            }
            #pragma unroll
            for (int o = 16; o; o >>= 1) {
                float v2 = __shfl_xor_sync(0xffffffffu, v, o);
                int   i2 = __shfl_xor_sync(0xffffffffu, i, o);
                if (v2 > v || (v2 == v && i2 < i)) { v = v2; i = i2; }
            }
            if (t == 0) {
                g_cand[bn * KCAND + k] = i;
                vals[i] = NEG_INF;
            }
        }
        __syncthreads();
    }
}

// =========================================================================
// K4: selection — node exact re-rank (warp-per-candidate dot2) -> top-8
// nodes; token sims in PLAIN FP32 -> rank-count top-12 -> exact dot2
// re-rank of only those 12 -> top-8 tokens -> g_sel.
// 512 threads, <=64 regs (launch_bounds), ~20 KB smem.
// =========================================================================
__global__ __launch_bounds__(512, 2) void k_tok_sel(const float* __restrict__ h) {
    __shared__ __align__(16) float sQ[PD];       // own node row (16 KB)
    __shared__ __align__(16) float ssim[KNODE * PP];  // 336 fp32 prepass sims
    __shared__ double exd[KCAND];
    __shared__ int    scnd[KCAND];
    __shared__ int    snode[KNODE];
    __shared__ int    tcand[KTC];
    __shared__ double texd[KTC];

    int bn = blockIdx.x;
    int b = bn >> 10;
    int t = threadIdx.x, warp = t >> 5, lane = t & 31;

    const float4* q4 = (const float4*)(h + (size_t)bn * PD);
    float4* sQ4 = (float4*)sQ;
    for (int i = t; i < PD / 4; i += 512) sQ4[i] = q4[i];
    if (t < KCAND) scnd[t] = g_cand[bn * KCAND + t];
    __syncthreads();

    // ---- exact node sims: warp per candidate (12 of 16 warps, 1 round) ----
    if (warp < KCAND) {
        int m = scnd[warp];
        const float4* f4 = (const float4*)(h + (size_t)(b * NN + m) * PD);
        float hx = 0.f, lx = 0.f, hy = 0.f, ly = 0.f;
        float hz = 0.f, lz = 0.f, hw = 0.f, lw = 0.f;
        #pragma unroll 4
        for (int j = 0; j < 31; j++) {
            int i4 = j * 32 + lane;
            float4 a = sQ4[i4];
            float4 cc = f4[i4];
            dot2_step(a.x, cc.x, hx, lx);
            dot2_step(a.y, cc.y, hy, ly);
            dot2_step(a.z, cc.z, hz, lz);
            dot2_step(a.w, cc.w, hw, lw);
        }
        if (lane < 16) {
            int i4 = 992 + lane;
            float4 a = sQ4[i4];
            float4 cc = f4[i4];
            dot2_step(a.x, cc.x, hx, lx);
            dot2_step(a.y, cc.y, hy, ly);
            dot2_step(a.z, cc.z, hz, lz);
            dot2_step(a.w, cc.w, hw, lw);
        }
        double v = ((double)hx + lx) + ((double)hy + ly) +
                   ((double)hz + lz) + ((double)hw + lw);
        #pragma unroll
        for (int o = 16; o; o >>= 1) v += __shfl_xor_sync(0xffffffffu, v, o);
        if (lane == 0) exd[warp] = v * g_inv_node_d[bn] * g_inv_node_d[b * NN + m];
    }
    __syncthreads();

    if (t == 0) {
        unsigned used = 0;
        for (int k = 0; k < KNODE; k++) {
            int best = -1;
            for (int j = 0; j < KCAND; j++) {
                if (used & (1u << j)) continue;
                if (best < 0 || exd[j] > exd[best] ||
                    (exd[j] == exd[best] && scnd[j] < scnd[best])) best = j;
            }
            used |= (1u << best);
            snode[k] = scnd[best];
        }
    }
    __syncthreads();

    // ---- token sims, plain fp32 (prepass; per-thread, 1 round) ----
    const float4* tq4 = (const float4*)(sQ + (PP - 1) * DD);
    double qinv = g_inv_tok_d[bn * PP + PP - 1];
    if (t < KNODE * PP) {
        int kn = t / PP, p = t - kn * PP;
        int m = snode[kn];
        const float4* tp4 = (const float4*)(h + (((size_t)(b * NN + m)) * PP + p) * DD);
        float ax = 0.f, ay = 0.f, az = 0.f, aw = 0.f;
        #pragma unroll
        for (int j = 0; j < DD / 4; j++) {
            float4 a = tq4[j];
            float4 f = tp4[j];
            ax = fmaf(a.x, f.x, ax);
            ay = fmaf(a.y, f.y, ay);
            az = fmaf(a.z, f.z, az);
            aw = fmaf(a.w, f.w, aw);
        }
        float v = (ax + ay) + (az + aw);
        ssim[t] = (float)((double)v * qinv * g_inv_tok_d[(b * NN + m) * PP + p]);
    }
    __syncthreads();

    // ---- rank-count top-12 selection (no reduction passes) ----
    if (t < KNODE * PP) {
        float vt = ssim[t];
        const float4* s4 = (const float4*)ssim;
        int rank = 0;
        #pragma unroll 4
        for (int j4 = 0; j4 < (KNODE * PP) / 4; j4++) {
            float4 vv = s4[j4];
            int j = j4 * 4;
            rank += (vv.x > vt || (vv.x == vt && (j + 0) < t));
            rank += (vv.y > vt || (vv.y == vt && (j + 1) < t));
            rank += (vv.z > vt || (vv.z == vt && (j + 2) < t));
            rank += (vv.w > vt || (vv.w == vt && (j + 3) < t));
        }
        if (rank < KTC) tcand[rank] = t;          // ranks are unique
    }
    __syncthreads();

    // ---- exact re-rank of the 12 token candidates (warp per candidate) ----
    if (warp < KTC) {
        int c = tcand[warp];
        int kn = c / PP, p = c - kn * PP;
        int m = snode[kn];
        const float* tp = h + (((size_t)(b * NN + m)) * PP + p) * (size_t)DD;
        const float* sq = sQ + (PP - 1) * DD;
        float hi = 0.f, lo = 0.f;
        dot2_step(tp[lane],      sq[lane],      hi, lo);
        dot2_step(tp[lane + 32], sq[lane + 32], hi, lo);
        dot2_step(tp[lane + 64], sq[lane + 64], hi, lo);
        double v = (double)hi + (double)lo;
        #pragma unroll
        for (int o = 16; o; o >>= 1) v += __shfl_xor_sync(0xffffffffu, v, o);
        if (lane == 0) texd[warp] = v * qinv * g_inv_tok_d[(b * NN + m) * PP + p];
    }
    __syncthreads();

    if (t == 0) {
        unsigned used = 0;
        for (int k = 0; k < KTOK; k++) {
            int best = -1;
            for (int j = 0; j < KTC; j++) {
                if (used & (1u << j)) continue;
                if (best < 0 || texd[j] > texd[best] ||
                    (texd[j] == texd[best] && tcand[j] < tcand[best])) best = j;
            }
            used |= (1u << best);
            int c = tcand[best];
            int kn = c / PP, p = c - kn * PP;
            g_sel[bn * KTOK + k] = snode[kn] * 64 + p;
        }
    }
}

// =========================================================================
// K5: sk linear — gather 64 selected tokens/block, x @ W^T + b + nt.
// =========================================================================
__global__ __launch_bounds__(256) void k_sklin(const float* __restrict__ h,
                                               const float* __restrict__ W,
                                               const float* __restrict__ bias,
                                               const float* __restrict__ ntok,
                                               float* __restrict__ out) {
    __shared__ __align__(16) float sXT[DD * 68];
    __shared__ __align__(16) float sWT[DD * 98];
    __shared__ size_t rowoff[64];

    int r0 = blockIdx.x * 64;
    int t = threadIdx.x;

    if (t < 64) {
        int rr = r0 + t;
        int bn = rr >> 3;
        int b = bn >> 10;
        int s = g_sel[bn * KTOK + (rr & 7)];
        int m = s >> 6, p = s & 63;
        rowoff[t] = (((size_t)(b * NN + m)) * PP + p) * (size_t)DD;
    }
    __syncthreads();

    for (int i = t; i < 64 * DD; i += 256) {
        int r = i / DD, d = i - r * DD;
        sXT[d * 68 + r] = h[rowoff[r] + d];
    }
    for (int i = t; i < DD * DD; i += 256) {
        int e = i / DD, d = i - e * DD;
        sWT[d * 98 + e] = W[i];
    }
    __syncthreads();

    float nt = ntok[0];
    int tx = t & 15, ty = t >> 4;
    unsigned long long acc[4][3];
    #pragma unroll
    for (int i = 0; i < 4; i++)
        #pragma unroll
        for (int j = 0; j < 3; j++)
            acc[i][j] = pk2(bias[tx * 6 + 2 * j] + nt, bias[tx * 6 + 2 * j + 1] + nt);

    #pragma unroll 4
    for (int d = 0; d < DD; d++) {
        float4 xv = *(const float4*)(sXT + d * 68 + ty * 4);
        const unsigned long long* wp = (const unsigned long long*)(sWT + d * 98 + tx * 6);
        unsigned long long b0 = wp[0], b1 = wp[1], b2 = wp[2];
        float x[4] = {xv.x, xv.y, xv.z, xv.w};
        #pragma unroll
        for (int i = 0; i < 4; i++) {
            unsigned long long a = pk2(x[i], x[i]);
            fma2(acc[i][0], a, b0);
            fma2(acc[i][1], a, b1);
            fma2(acc[i][2], a, b2);
        }
    }

    #pragma unroll
    for (int i = 0; i < 4; i++) {
        int rr = r0 + ty * 4 + i;
        int bn = rr >> 3, k = rr & 7;
        float* orow = out + (((size_t)bn) * POUT + PP + k) * (size_t)DD + tx * 6;
        #pragma unroll
        for (int j = 0; j < 3; j++) {
            float lo, hi;
            upk2(acc[i][j], lo, hi);
            orow[2 * j] = lo;
            orow[2 * j + 1] = hi;
        }
    }
}

// =========================================================================
// K6: hf = h @ W^T + b -> out[:, :, 0:42, :].  f32x2 packed FFMA.
// =========================================================================
__global__ __launch_bounds__(256) void k_hf(const float* __restrict__ h,
                                            const float* __restrict__ W,
                                            const float* __restrict__ bias,
                                            float* __restrict__ out) {
    extern __shared__ __align__(16) float dyn[];
    float* sXT = dyn;                 // [DD][68]
    float* sWT = dyn + DD * 68;       // [DD][98]

    int r0 = blockIdx.x * 64;
    int t = threadIdx.x;

    const float* Xbase = h + (size_t)r0 * DD;
    for (int i = t; i < 64 * DD; i += 256) {
        int r = i / DD, d = i - r * DD;
        sXT[d * 68 + r] = Xbase[i];
    }
    for (int i = t; i < DD * DD; i += 256) {
        int e = i / DD, d = i - e * DD;
        sWT[d * 98 + e] = W[i];
    }
    __syncthreads();

    int tx = t & 15, ty = t >> 4;
    unsigned long long acc[4][3];
    #pragma unroll
    for (int i = 0; i < 4; i++)
        #pragma unroll
        for (int j = 0; j < 3; j++)
            acc[i][j] = pk2(bias[tx * 6 + 2 * j], bias[tx * 6 + 2 * j + 1]);

    #pragma unroll 4
    for (int d = 0; d < DD; d++) {
        float4 xv = *(const float4*)(sXT + d * 68 + ty * 4);
        const unsigned long long* wp = (const unsigned long long*)(sWT + d * 98 + tx * 6);
        unsigned long long b0 = wp[0], b1 = wp[1], b2 = wp[2];
        float x[4] = {xv.x, xv.y, xv.z, xv.w};
        #pragma unroll
        for (int i = 0; i < 4; i++) {
            unsigned long long a = pk2(x[i], x[i]);
            fma2(acc[i][0], a, b0);
            fma2(acc[i][1], a, b1);
            fma2(acc[i][2], a, b2);
        }
    }

    #pragma unroll
    for (int i = 0; i < 4; i++) {
        int r = r0 + ty * 4 + i;
        int bn = r / PP, p = r - bn * PP;
        float* orow = out + (((size_t)bn) * POUT + p) * (size_t)DD + tx * 6;
        #pragma unroll
        for (int j = 0; j < 3; j++) {
            float lo, hi;
            upk2(acc[i][j], lo, hi);
            orow[2 * j] = lo;
            orow[2 * j + 1] = hi;
        }
    }
}

// =========================================================================
extern "C" void kernel_launch(void* const* d_in, const int* in_sizes, int n_in,
                              void* d_out, int out_size) {
    const float* h    = (const float*)d_in[0];
    const float* W    = (const float*)d_in[1];
    const float* bias = (const float*)d_in[2];
    const float* ntok = (const float*)d_in[3];
    float* out = (float*)d_out;

    k_convnorm<<<BB * NN, 128>>>(h);                                 // 1

    cudaFuncSetAttribute(k_sim_mma, cudaFuncAttributeMaxDynamicSharedMemorySize, 65536);
    dim3 g2(NN / 128, NN / 128, BB);
    k_sim_mma<<<g2, 256, 65536>>>();                                 // 2

    k_topk_node<<<BB * NN, 256>>>();                                 // 3

    k_tok_sel<<<BB * NN, 512>>>(h);                                  // 4  <- profiled slot

    k_sklin<<<(BB * NN * KTOK) / 64, 256>>>(h, W, bias, ntok, out);  // 5

    size_t hf_smem = (size_t)(DD * 68 + DD * 98) * sizeof(float);
    cudaFuncSetAttribute(k_hf, cudaFuncAttributeMaxDynamicSharedMemorySize, (int)hf_smem);
    k_hf<<<(BB * NN * PP) / 64, 256, hf_smem>>>(h, W, bias, out);    // 6
}

// round 11
// speedup vs baseline: 1.1215x; 1.1215x over previous
#include <cuda_runtime.h>
#include <cuda_bf16.h>
#include <cstdint>
#include <math.h>

#define BB 4
#define NN 1024
#define PP 42
#define DD 96
#define PD 4032          // PP*DD
#define KNODE 8
#define KCAND 12         // node prepass candidates
#define KTOK 8
#define KTC 12           // token prepass candidates
#define POUT 50          // PP + KTOK
#define EPSD 1e-7

#define NEG_INF __int_as_float(0xff800000)

// ---------------- scratch (device globals; no allocation) ----------------
__device__ float  g_sim[BB * NN * NN];
__device__ __align__(16) __nv_bfloat16 g_hbf[BB * NN * PD];
__device__ double g_inv_node_d[BB * NN];
__device__ float  g_inv_node_f[BB * NN];
__device__ double g_inv_tok_d[BB * NN * PP];
__device__ int    g_cand[BB * NN * KCAND];
__device__ int    g_node[BB * NN * KNODE];
__device__ __align__(16) float g_tsim[BB * NN * KNODE * PP];  // 336 per bn
__device__ int    g_sel[BB * NN * KTOK];      // selected tokens: m*64 + p

// ---------------- compensated arithmetic helpers --------------------------
__device__ __forceinline__ void two_sum(float a, float b, float& s, float& e) {
    s = a + b;
    float z = s - a;
    e = (a - (s - z)) + (b - z);
}
__device__ __forceinline__ void dot2_step(float a, float b, float& hi, float& lo) {
    float p = a * b;
    float ep = fmaf(a, b, -p);
    float s, e;
    two_sum(hi, p, s, e);
    hi = s;
    lo += e + ep;
}

__device__ __forceinline__ void cp16(uint32_t s, const void* g) {
    asm volatile("cp.async.cg.shared.global [%0], [%1], 16;\n" :: "r"(s), "l"(g));
}

// ---------------- packed f32x2 helpers (Blackwell FFMA2) ------------------
__device__ __forceinline__ unsigned long long pk2(float lo, float hi) {
    unsigned long long r;
    asm("mov.b64 %0, {%1, %2};" : "=l"(r) : "f"(lo), "f"(hi));
    return r;
}
__device__ __forceinline__ void fma2(unsigned long long& d,
                                     unsigned long long a, unsigned long long b) {
    asm("fma.rn.f32x2 %0, %1, %2, %0;" : "+l"(d) : "l"(a), "l"(b));
}
__device__ __forceinline__ void upk2(unsigned long long v, float& lo, float& hi) {
    asm("mov.b64 {%0, %1}, %2;" : "=f"(lo), "=f"(hi) : "l"(v));
}

// =========================================================================
// K1: FUSED bf16 conversion + exact token/node norms.
// =========================================================================
__global__ __launch_bounds__(128) void k_convnorm(const float* __restrict__ h) {
    int bn = blockIdx.x;
    const float* base = h + (size_t)bn * PD;
    __shared__ double s_node[4];
    int t = threadIdx.x, warp = t >> 5, lane = t & 31;

    const float4* b4 = (const float4*)base;
    uint2* o2 = (uint2*)(g_hbf + (size_t)bn * PD);
    for (int i = t; i < PD / 4; i += 128) {
        float4 v = b4[i];
        __nv_bfloat162 lo = __floats2bfloat162_rn(v.x, v.y);
        __nv_bfloat162 hi = __floats2bfloat162_rn(v.z, v.w);
        uint2 pkv;
        pkv.x = *(uint32_t*)&lo;
        pkv.y = *(uint32_t*)&hi;
        o2[i] = pkv;
    }

    double nodesum = 0.0;
    for (int p = warp; p < PP; p += 4) {
        const float* tp = base + p * DD;
        float hi = 0.f, lo = 0.f;
        float v0 = tp[lane], v1 = tp[lane + 32], v2 = tp[lane + 64];
        dot2_step(v0, v0, hi, lo);
        dot2_step(v1, v1, hi, lo);
        dot2_step(v2, v2, hi, lo);
        double s = (double)hi + (double)lo;
        #pragma unroll
        for (int o = 16; o; o >>= 1) s += __shfl_xor_sync(0xffffffffu, s, o);
        if (lane == 0) g_inv_tok_d[bn * PP + p] = 1.0 / (sqrt(s) + EPSD);
        nodesum += s;
    }
    if (lane == 0) s_node[warp] = nodesum;
    __syncthreads();
    if (t == 0) {
        double tt = s_node[0] + s_node[1] + s_node[2] + s_node[3];
        double inv = 1.0 / (sqrt(tt) + EPSD);
        g_inv_node_d[bn] = inv;
        g_inv_node_f[bn] = (float)inv;
    }
}

// =========================================================================
// K2: bf16 tensor-core prepass GEMM (symmetric, upper tiles + mirror).
// =========================================================================
__global__ void __launch_bounds__(256, 2) k_sim_mma() {
    if (blockIdx.y > blockIdx.x) return;
    extern __shared__ __align__(16) unsigned char smraw[];
    const int t = threadIdx.x;
    const int lane = t & 31, warp = t >> 5;
    const int warp_m = warp >> 2, warp_n = warp & 3;
    const int bz = blockIdx.z;
    const int rowBase = blockIdx.y * 128, colBase = blockIdx.x * 128;
    const __nv_bfloat16* base = g_hbf + (size_t)bz * NN * PD;
    uint32_t s0 = (uint32_t)__cvta_generic_to_shared(smraw);

    float acc[4][4][4];
    #pragma unroll
    for (int i = 0; i < 4; i++)
        #pragma unroll
        for (int j = 0; j < 4; j++)
            #pragma unroll
            for (int q = 0; q < 4; q++) acc[i][j][q] = 0.f;

    auto issue = [&](int it, int buf) {
        int k0 = it * 64;
        uint32_t sbuf = s0 + buf * 32768;
        #pragma unroll
        for (int i = 0; i < 4; i++) {
            int u = t + 256 * i;
            int r = u >> 3, c = u & 7;
            uint32_t soff = r * 128 + ((c ^ (r & 7)) << 4);
            cp16(sbuf + soff, base + (size_t)(rowBase + r) * PD + k0 + c * 8);
            cp16(sbuf + 16384 + soff, base + (size_t)(colBase + r) * PD + k0 + c * 8);
        }
        asm volatile("cp.async.commit_group;\n");
    };

    issue(0, 0);
    for (int it = 0; it < 63; it++) {
        if (it < 62) {
            issue(it + 1, (it + 1) & 1);
            asm volatile("cp.async.wait_group 1;\n");
        } else {
            asm volatile("cp.async.wait_group 0;\n");
        }
        __syncthreads();
        uint32_t sA = s0 + (it & 1) * 32768;
        uint32_t sB = sA + 16384;
        #pragma unroll
        for (int kk = 0; kk < 4; kk++) {
            uint32_t a[4][4], bf[4][2];
            #pragma unroll
            for (int mi = 0; mi < 4; mi++) {
                int row = warp_m * 64 + mi * 16 + ((lane >> 3) & 1) * 8 + (lane & 7);
                int ch = kk * 2 + (lane >> 4);
                uint32_t addr = sA + row * 128 + ((ch ^ (row & 7)) << 4);
                asm volatile("ldmatrix.sync.aligned.m8n8.x4.shared.b16 {%0,%1,%2,%3}, [%4];\n"
                    : "=r"(a[mi][0]), "=r"(a[mi][1]), "=r"(a[mi][2]), "=r"(a[mi][3]) : "r"(addr));
            }
            #pragma unroll
            for (int call = 0; call < 2; call++) {
                int row = warp_n * 32 + call * 16 + ((lane >> 4) & 1) * 8 + (lane & 7);
                int ch = kk * 2 + ((lane >> 3) & 1);
                uint32_t addr = sB + row * 128 + ((ch ^ (row & 7)) << 4);
                uint32_t r0, r1, r2, r3;
                asm volatile("ldmatrix.sync.aligned.m8n8.x4.shared.b16 {%0,%1,%2,%3}, [%4];\n"
                    : "=r"(r0), "=r"(r1), "=r"(r2), "=r"(r3) : "r"(addr));
                bf[call * 2][0] = r0; bf[call * 2][1] = r1;
                bf[call * 2 + 1][0] = r2; bf[call * 2 + 1][1] = r3;
            }
            #pragma unroll
            for (int mi = 0; mi < 4; mi++)
                #pragma unroll
                for (int ni = 0; ni < 4; ni++)
                    asm volatile("mma.sync.aligned.m16n8k16.row.col.f32.bf16.bf16.f32 "
                        "{%0,%1,%2,%3}, {%4,%5,%6,%7}, {%8,%9}, {%0,%1,%2,%3};\n"
                        : "+f"(acc[mi][ni][0]), "+f"(acc[mi][ni][1]),
                          "+f"(acc[mi][ni][2]), "+f"(acc[mi][ni][3])
                        : "r"(a[mi][0]), "r"(a[mi][1]), "r"(a[mi][2]), "r"(a[mi][3]),
                          "r"(bf[ni][0]), "r"(bf[ni][1]));
        }
        __syncthreads();
    }

    float* C = g_sim + (size_t)bz * NN * NN;
    const bool offdiag = (rowBase != colBase);
    #pragma unroll
    for (int mi = 0; mi < 4; mi++) {
        int r = rowBase + warp_m * 64 + mi * 16 + (lane >> 2);
        #pragma unroll
        for (int ni = 0; ni < 4; ni++) {
            int c = colBase + warp_n * 32 + ni * 8 + (lane & 3) * 2;
            *(float2*)(C + (size_t)r * NN + c) = make_float2(acc[mi][ni][0], acc[mi][ni][1]);
            *(float2*)(C + (size_t)(r + 8) * NN + c) = make_float2(acc[mi][ni][2], acc[mi][ni][3]);
            if (offdiag) {
                C[(size_t)c * NN + r]           = acc[mi][ni][0];
                C[(size_t)(c + 1) * NN + r]     = acc[mi][ni][1];
                C[(size_t)c * NN + r + 8]       = acc[mi][ni][2];
                C[(size_t)(c + 1) * NN + r + 8] = acc[mi][ni][3];
            }
        }
    }
}

// =========================================================================
// K3: prepass — normalize row, zero diag, select top-12 node candidates.
// =========================================================================
__global__ __launch_bounds__(256) void k_topk_node() {
    int bn = blockIdx.x;
    int b = bn >> 10, n = bn & 1023;
    __shared__ float vals[NN];
    __shared__ float rv[256];
    __shared__ int   ri[256];
    int t = threadIdx.x;
    float invn = g_inv_node_f[bn];
    const float* row = g_sim + (size_t)b * NN * NN + (size_t)n * NN;
    for (int m = t; m < NN; m += 256) {
        vals[m] = (m == n) ? 0.f : row[m] * invn * g_inv_node_f[b * NN + m];
    }
    __syncthreads();
    for (int k = 0; k < KCAND; k++) {
        float bv = NEG_INF; int bi = 0;
        #pragma unroll
        for (int j = 0; j < 4; j++) {
            int m = t + j * 256;
            float v = vals[m];
            if (v > bv) { bv = v; bi = m; }
        }
        rv[t] = bv; ri[t] = bi;
        __syncthreads();
        if (t < 32) {
            float v = rv[t]; int i = ri[t];
            #pragma unroll
            for (int j = 1; j < 8; j++) {
                float v2 = rv[t + j * 32]; int i2 = ri[t + j * 32];
                if (v2 > v || (v2 == v && i2 < i)) { v = v2; i = i2; }
            }
            #pragma unroll
            for (int o = 16; o; o >>= 1) {
                float v2 = __shfl_xor_sync(0xffffffffu, v, o);
                int   i2 = __shfl_xor_sync(0xffffffffu, i, o);
                if (v2 > v || (v2 == v && i2 < i)) { v = v2; i = i2; }
            }
            if (t == 0) {
                g_cand[bn * KCAND + k] = i;
                vals[i] = NEG_INF;
            }
        }
        __syncthreads();
    }
}

// =========================================================================
// K4: exact node re-rank.  768 threads = 24 warps = 2 warps per candidate
// (half-row each, coalesced, double MLP).  -> g_node top-8.
// =========================================================================
__global__ __launch_bounds__(768) void k_nrerank(const float* __restrict__ h) {
    __shared__ __align__(16) float sQ[PD];
    __shared__ double part[2 * KCAND];
    __shared__ int    scnd[KCAND];

    int bn = blockIdx.x;
    int b = bn >> 10;
    int t = threadIdx.x, warp = t >> 5, lane = t & 31;

    const float4* q4 = (const float4*)(h + (size_t)bn * PD);
    float4* sQ4 = (float4*)sQ;
    for (int i = t; i < PD / 4; i += 768) sQ4[i] = q4[i];
    if (t < KCAND) scnd[t] = g_cand[bn * KCAND + t];
    __syncthreads();

    if (warp < 2 * KCAND) {
        int c = warp >> 1, half = warp & 1;
        int m = scnd[c];
        const float4* f4 = (const float4*)(h + (size_t)(b * NN + m) * PD);
        int base4 = half * 504;                  // 1008 float4 total, 504 per half
        float hx = 0.f, lx = 0.f, hy = 0.f, ly = 0.f;
        float hz = 0.f, lz = 0.f, hw = 0.f, lw = 0.f;
        #pragma unroll 5
        for (int j = 0; j < 15; j++) {
            int i4 = base4 + j * 32 + lane;
            float4 a = sQ4[i4];
            float4 cc = f4[i4];
            dot2_step(a.x, cc.x, hx, lx);
            dot2_step(a.y, cc.y, hy, ly);
            dot2_step(a.z, cc.z, hz, lz);
            dot2_step(a.w, cc.w, hw, lw);
        }
        if (lane < 24) {                         // tail 504-480=24
            int i4 = base4 + 480 + lane;
            float4 a = sQ4[i4];
            float4 cc = f4[i4];
            dot2_step(a.x, cc.x, hx, lx);
            dot2_step(a.y, cc.y, hy, ly);
            dot2_step(a.z, cc.z, hz, lz);
            dot2_step(a.w, cc.w, hw, lw);
        }
        double v = ((double)hx + lx) + ((double)hy + ly) +
                   ((double)hz + lz) + ((double)hw + lw);
        #pragma unroll
        for (int o = 16; o; o >>= 1) v += __shfl_xor_sync(0xffffffffu, v, o);
        if (lane == 0) part[warp] = v;
    }
    __syncthreads();

    if (t == 0) {
        double exd[KCAND];
        #pragma unroll
        for (int c = 0; c < KCAND; c++)
            exd[c] = (part[2 * c] + part[2 * c + 1]) *
                     g_inv_node_d[bn] * g_inv_node_d[b * NN + scnd[c]];
        unsigned used = 0;
        for (int k = 0; k < KNODE; k++) {
            int best = -1;
            for (int j = 0; j < KCAND; j++) {
                if (used & (1u << j)) continue;
                if (best < 0 || exd[j] > exd[best] ||
                    (exd[j] == exd[best] && scnd[j] < scnd[best])) best = j;
            }
            used |= (1u << best);
            g_node[bn * KNODE + k] = scnd[best];
        }
    }
}

// =========================================================================
// K5: token sims (fp32 prepass).  One block per (bn, kn): stage node row
// into padded smem (coalesced), 42 threads compute dots from smem
// (conflict-free, pad 97) -> g_tsim.
// =========================================================================
__global__ __launch_bounds__(128) void k_tsim(const float* __restrict__ h) {
    __shared__ float sR[PP * 97];                // 16.3 KB, padded rows
    __shared__ float sq[DD];

    int bk = blockIdx.x;
    int bn = bk >> 3, kn = bk & 7;
    int b = bn >> 10;
    int t = threadIdx.x;

    int m = g_node[bn * KNODE + kn];
    const float4* row4 = (const float4*)(h + (size_t)(b * NN + m) * PD);
    for (int i4 = t; i4 < PD / 4; i4 += 128) {
        int p = i4 / 24, d4 = i4 - p * 24;       // 24 float4 per token
        float4 v = row4[i4];
        float* dst = &sR[p * 97 + d4 * 4];
        dst[0] = v.x; dst[1] = v.y; dst[2] = v.z; dst[3] = v.w;
    }
    if (t < DD / 4) {
        float4 v = ((const float4*)(h + ((size_t)bn * PP + (PP - 1)) * DD))[t];
        float* dst = &sq[t * 4];
        dst[0] = v.x; dst[1] = v.y; dst[2] = v.z; dst[3] = v.w;
    }
    __syncthreads();

    if (t < PP) {
        const float* r = &sR[t * 97];
        float a0 = 0.f, a1 = 0.f, a2 = 0.f, a3 = 0.f;
        #pragma unroll 8
        for (int d = 0; d < DD; d += 4) {
            a0 = fmaf(r[d],     sq[d],     a0);
            a1 = fmaf(r[d + 1], sq[d + 1], a1);
            a2 = fmaf(r[d + 2], sq[d + 2], a2);
            a3 = fmaf(r[d + 3], sq[d + 3], a3);
        }
        double v = (double)((a0 + a1) + (a2 + a3));
        v = v * g_inv_tok_d[bn * PP + PP - 1] * g_inv_tok_d[(b * NN + m) * PP + t];
        g_tsim[(size_t)bn * (KNODE * PP) + kn * PP + t] = (float)v;
    }
}

// =========================================================================
// K6: token select — rank-count top-12 of 336 fp32 sims, exact dot2
// re-rank of the 12, final top-8 -> g_sel.
// =========================================================================
__global__ __launch_bounds__(128) void k_tsel(const float* __restrict__ h) {
    __shared__ __align__(16) float ss[KNODE * PP];   // 336
    __shared__ float sq[DD];
    __shared__ int    tcand[KTC];
    __shared__ double texd[KTC];
    __shared__ int    snode[KNODE];

    int bn = blockIdx.x;
    int b = bn >> 10;
    int t = threadIdx.x, warp = t >> 5, lane = t & 31;

    const float4* ts4 = (const float4*)(g_tsim + (size_t)bn * (KNODE * PP));
    if (t < (KNODE * PP) / 4) ((float4*)ss)[t] = ts4[t];
    if (t < DD) sq[t] = h[((size_t)bn * PP + (PP - 1)) * DD + t];
    if (t < KNODE) snode[t] = g_node[bn * KNODE + t];
    __syncthreads();

    // rank-count top-12 (ties -> lower index; ranks unique)
    for (int c = t; c < KNODE * PP; c += 128) {
        float vt = ss[c];
        const float4* s4 = (const float4*)ss;
        int rank = 0;
        #pragma unroll 4
        for (int j4 = 0; j4 < (KNODE * PP) / 4; j4++) {
            float4 vv = s4[j4];
            int j = j4 * 4;
            rank += (vv.x > vt || (vv.x == vt && (j + 0) < c));
            rank += (vv.y > vt || (vv.y == vt && (j + 1) < c));
            rank += (vv.z > vt || (vv.z == vt && (j + 2) < c));
            rank += (vv.w > vt || (vv.w == vt && (j + 3) < c));
        }
        if (rank < KTC) tcand[rank] = c;
    }
    __syncthreads();

    // exact re-rank of the 12 (warp per candidate, 3 rounds)
    for (int cc = warp; cc < KTC; cc += 4) {
        int c = tcand[cc];
        int kn = c / PP, p = c - kn * PP;
        int m = snode[kn];
        const float* tp = h + (((size_t)(b * NN + m)) * PP + p) * (size_t)DD;
        float hi = 0.f, lo = 0.f;
        dot2_step(tp[lane],      sq[lane],      hi, lo);
        dot2_step(tp[lane + 32], sq[lane + 32], hi, lo);
        dot2_step(tp[lane + 64], sq[lane + 64], hi, lo);
        double v = (double)hi + (double)lo;
        #pragma unroll
        for (int o = 16; o; o >>= 1) v += __shfl_xor_sync(0xffffffffu, v, o);
        if (lane == 0)
            texd[cc] = v * g_inv_tok_d[bn * PP + PP - 1] *
                       g_inv_tok_d[(b * NN + m) * PP + p];
    }
    __syncthreads();

    if (t == 0) {
        unsigned used = 0;
        for (int k = 0; k < KTOK; k++) {
            int best = -1;
            for (int j = 0; j < KTC; j++) {
                if (used & (1u << j)) continue;
                if (best < 0 || texd[j] > texd[best] ||
                    (texd[j] == texd[best] && tcand[j] < tcand[best])) best = j;
            }
            used |= (1u << best);
            int c = tcand[best];
            int kn = c / PP, p = c - kn * PP;
            g_sel[bn * KTOK + k] = snode[kn] * 64 + p;
        }
    }
}

// =========================================================================
// K7: sk linear — gather 64 selected tokens/block, x @ W^T + b + nt.
// =========================================================================
__global__ __launch_bounds__(256) void k_sklin(const float* __restrict__ h,
                                               const float* __restrict__ W,
                                               const float* __restrict__ bias,
                                               const float* __restrict__ ntok,
                                               float* __restrict__ out) {
    __shared__ __align__(16) float sXT[DD * 68];
    __shared__ __align__(16) float sWT[DD * 98];
    __shared__ size_t rowoff[64];

    int r0 = blockIdx.x * 64;
    int t = threadIdx.x;

    if (t < 64) {
        int rr = r0 + t;
        int bn = rr >> 3;
        int b = bn >> 10;
        int s = g_sel[bn * KTOK + (rr & 7)];
        int m = s >> 6, p = s & 63;
        rowoff[t] = (((size_t)(b * NN + m)) * PP + p) * (size_t)DD;
    }
    __syncthreads();

    for (int i = t; i < 64 * DD; i += 256) {
        int r = i / DD, d = i - r * DD;
        sXT[d * 68 + r] = h[rowoff[r] + d];
    }
    for (int i = t; i < DD * DD; i += 256) {
        int e = i / DD, d = i - e * DD;
        sWT[d * 98 + e] = W[i];
    }
    __syncthreads();

    float nt = ntok[0];
    int tx = t & 15, ty = t >> 4;
    unsigned long long acc[4][3];
    #pragma unroll
    for (int i = 0; i < 4; i++)
        #pragma unroll
        for (int j = 0; j < 3; j++)
            acc[i][j] = pk2(bias[tx * 6 + 2 * j] + nt, bias[tx * 6 + 2 * j + 1] + nt);

    #pragma unroll 4
    for (int d = 0; d < DD; d++) {
        float4 xv = *(const float4*)(sXT + d * 68 + ty * 4);
        const unsigned long long* wp = (const unsigned long long*)(sWT + d * 98 + tx * 6);
        unsigned long long b0 = wp[0], b1 = wp[1], b2 = wp[2];
        float x[4] = {xv.x, xv.y, xv.z, xv.w};
        #pragma unroll
        for (int i = 0; i < 4; i++) {
            unsigned long long a = pk2(x[i], x[i]);
            fma2(acc[i][0], a, b0);
            fma2(acc[i][1], a, b1);
            fma2(acc[i][2], a, b2);
        }
    }

    #pragma unroll
    for (int i = 0; i < 4; i++) {
        int rr = r0 + ty * 4 + i;
        int bn = rr >> 3, k = rr & 7;
        float* orow = out + (((size_t)bn) * POUT + PP + k) * (size_t)DD + tx * 6;
        #pragma unroll
        for (int j = 0; j < 3; j++) {
            float lo, hi;
            upk2(acc[i][j], lo, hi);
            orow[2 * j] = lo;
            orow[2 * j + 1] = hi;
        }
    }
}

// =========================================================================
// K8: hf = h @ W^T + b -> out[:, :, 0:42, :].  f32x2 packed FFMA.
// =========================================================================
__global__ __launch_bounds__(256) void k_hf(const float* __restrict__ h,
                                            const float* __restrict__ W,
                                            const float* __restrict__ bias,
                                            float* __restrict__ out) {
    extern __shared__ __align__(16) float dyn[];
    float* sXT = dyn;                 // [DD][68]
    float* sWT = dyn + DD * 68;       // [DD][98]

    int r0 = blockIdx.x * 64;
    int t = threadIdx.x;

    const float* Xbase = h + (size_t)r0 * DD;
    for (int i = t; i < 64 * DD; i += 256) {
        int r = i / DD, d = i - r * DD;
        sXT[d * 68 + r] = Xbase[i];
    }
    for (int i = t; i < DD * DD; i += 256) {
        int e = i / DD, d = i - e * DD;
        sWT[d * 98 + e] = W[i];
    }
    __syncthreads();

    int tx = t & 15, ty = t >> 4;
    unsigned long long acc[4][3];
    #pragma unroll
    for (int i = 0; i < 4; i++)
        #pragma unroll
        for (int j = 0; j < 3; j++)
            acc[i][j] = pk2(bias[tx * 6 + 2 * j], bias[tx * 6 + 2 * j + 1]);

    #pragma unroll 4
    for (int d = 0; d < DD; d++) {
        float4 xv = *(const float4*)(sXT + d * 68 + ty * 4);
        const unsigned long long* wp = (const unsigned long long*)(sWT + d * 98 + tx * 6);
        unsigned long long b0 = wp[0], b1 = wp[1], b2 = wp[2];
        float x[4] = {xv.x, xv.y, xv.z, xv.w};
        #pragma unroll
        for (int i = 0; i < 4; i++) {
            unsigned long long a = pk2(x[i], x[i]);
            fma2(acc[i][0], a, b0);
            fma2(acc[i][1], a, b1);
            fma2(acc[i][2], a, b2);
        }
    }

    #pragma unroll
    for (int i = 0; i < 4; i++) {
        int r = r0 + ty * 4 + i;
        int bn = r / PP, p = r - bn * PP;
        float* orow = out + (((size_t)bn) * POUT + p) * (size_t)DD + tx * 6;
        #pragma unroll
        for (int j = 0; j < 3; j++) {
            float lo, hi;
            upk2(acc[i][j], lo, hi);
            orow[2 * j] = lo;
            orow[2 * j + 1] = hi;
        }
    }
}

// =========================================================================
extern "C" void kernel_launch(void* const* d_in, const int* in_sizes, int n_in,
                              void* d_out, int out_size) {
    const float* h    = (const float*)d_in[0];
    const float* W    = (const float*)d_in[1];
    const float* bias = (const float*)d_in[2];
    const float* ntok = (const float*)d_in[3];
    float* out = (float*)d_out;

    k_convnorm<<<BB * NN, 128>>>(h);                                 // 1

    cudaFuncSetAttribute(k_sim_mma, cudaFuncAttributeMaxDynamicSharedMemorySize, 65536);
    dim3 g2(NN / 128, NN / 128, BB);
    k_sim_mma<<<g2, 256, 65536>>>();                                 // 2

    k_topk_node<<<BB * NN, 256>>>();                                 // 3

    k_nrerank<<<BB * NN, 768>>>(h);                                  // 4  <- profiled slot

    k_tsim<<<BB * NN * KNODE, 128>>>(h);                             // 5

    k_tsel<<<BB * NN, 128>>>(h);                                     // 6

    k_sklin<<<(BB * NN * KTOK) / 64, 256>>>(h, W, bias, ntok, out);  // 7

    size_t hf_smem = (size_t)(DD * 68 + DD * 98) * sizeof(float);
    cudaFuncSetAttribute(k_hf, cudaFuncAttributeMaxDynamicSharedMemorySize, (int)hf_smem);
    k_hf<<<(BB * NN * PP) / 64, 256, hf_smem>>>(h, W, bias, out);    // 8
}

// round 14
// speedup vs baseline: 1.3065x; 1.1649x over previous
#include <cuda_runtime.h>
#include <cuda_bf16.h>
#include <cstdint>
#include <math.h>

#define BB 4
#define NN 1024
#define PP 42
#define DD 96
#define PD 4032          // PP*DD
#define KNODE 8
#define KCAND 12         // node prepass candidates
#define KTOK 8
#define KTC 12           // token prepass candidates
#define POUT 50          // PP + KTOK
#define EPSD 1e-7
#define DELTA_NODE 1e-5f // ambiguity gate (prepass err ~1.5e-7 rms)

#define NEG_INF __int_as_float(0xff800000)

// ---------------- scratch (device globals; no allocation) ----------------
__device__ float  g_sim[BB * NN * NN];
__device__ __align__(16) __nv_bfloat16 g_hbf[BB * NN * PD];   // hi part
__device__ __align__(16) __nv_bfloat16 g_hlo[BB * NN * PD];   // lo part
__device__ double g_inv_node_d[BB * NN];
__device__ float  g_inv_node_f[BB * NN];
__device__ double g_inv_tok_d[BB * NN * PP];
__device__ int    g_node[BB * NN * KNODE];
__device__ __align__(16) float g_tsim[BB * NN * KNODE * PP];  // 336 per bn
__device__ int    g_sel[BB * NN * KTOK];      // selected tokens: m*64 + p

// ---------------- compensated arithmetic helpers --------------------------
__device__ __forceinline__ void two_sum(float a, float b, float& s, float& e) {
    s = a + b;
    float z = s - a;
    e = (a - (s - z)) + (b - z);
}
__device__ __forceinline__ void dot2_step(float a, float b, float& hi, float& lo) {
    float p = a * b;
    float ep = fmaf(a, b, -p);
    float s, e;
    two_sum(hi, p, s, e);
    hi = s;
    lo += e + ep;
}

__device__ __forceinline__ void cp16(uint32_t s, const void* g) {
    asm volatile("cp.async.cg.shared.global [%0], [%1], 16;\n" :: "r"(s), "l"(g));
}

// ---------------- packed f32x2 helpers (Blackwell FFMA2) ------------------
__device__ __forceinline__ unsigned long long pk2(float lo, float hi) {
    unsigned long long r;
    asm("mov.b64 %0, {%1, %2};" : "=l"(r) : "f"(lo), "f"(hi));
    return r;
}
__device__ __forceinline__ void fma2(unsigned long long& d,
                                     unsigned long long a, unsigned long long b) {
    asm("fma.rn.f32x2 %0, %1, %2, %0;" : "+l"(d) : "l"(a), "l"(b));
}
__device__ __forceinline__ void upk2(unsigned long long v, float& lo, float& hi) {
    asm("mov.b64 {%0, %1}, %2;" : "=f"(lo), "=f"(hi) : "l"(v));
}

// =========================================================================
// K1: bf16 SPLIT conversion (hi+lo) + exact token/node norms.
// =========================================================================
__global__ __launch_bounds__(128) void k_convnorm(const float* __restrict__ h) {
    int bn = blockIdx.x;
    const float* base = h + (size_t)bn * PD;
    __shared__ double s_node[4];
    int t = threadIdx.x, warp = t >> 5, lane = t & 31;

    const float4* b4 = (const float4*)base;
    uint2* ohi = (uint2*)(g_hbf + (size_t)bn * PD);
    uint2* olo = (uint2*)(g_hlo + (size_t)bn * PD);
    for (int i = t; i < PD / 4; i += 128) {
        float4 v = b4[i];
        __nv_bfloat16 h0 = __float2bfloat16_rn(v.x);
        __nv_bfloat16 h1 = __float2bfloat16_rn(v.y);
        __nv_bfloat16 h2 = __float2bfloat16_rn(v.z);
        __nv_bfloat16 h3 = __float2bfloat16_rn(v.w);
        __nv_bfloat162 hp0 = __floats2bfloat162_rn(0.f, 0.f);
        hp0.x = h0; hp0.y = h1;
        __nv_bfloat162 hp1; hp1.x = h2; hp1.y = h3;
        uint2 pkh;
        pkh.x = *(uint32_t*)&hp0;
        pkh.y = *(uint32_t*)&hp1;
        ohi[i] = pkh;
        __nv_bfloat162 lp0, lp1;
        lp0.x = __float2bfloat16_rn(v.x - __bfloat162float(h0));
        lp0.y = __float2bfloat16_rn(v.y - __bfloat162float(h1));
        lp1.x = __float2bfloat16_rn(v.z - __bfloat162float(h2));
        lp1.y = __float2bfloat16_rn(v.w - __bfloat162float(h3));
        uint2 pkl;
        pkl.x = *(uint32_t*)&lp0;
        pkl.y = *(uint32_t*)&lp1;
        olo[i] = pkl;
    }

    double nodesum = 0.0;
    for (int p = warp; p < PP; p += 4) {
        const float* tp = base + p * DD;
        float hi = 0.f, lo = 0.f;
        float v0 = tp[lane], v1 = tp[lane + 32], v2 = tp[lane + 64];
        dot2_step(v0, v0, hi, lo);
        dot2_step(v1, v1, hi, lo);
        dot2_step(v2, v2, hi, lo);
        double s = (double)hi + (double)lo;
        #pragma unroll
        for (int o = 16; o; o >>= 1) s += __shfl_xor_sync(0xffffffffu, s, o);
        if (lane == 0) g_inv_tok_d[bn * PP + p] = 1.0 / (sqrt(s) + EPSD);
        nodesum += s;
    }
    if (lane == 0) s_node[warp] = nodesum;
    __syncthreads();
    if (t == 0) {
        double tt = s_node[0] + s_node[1] + s_node[2] + s_node[3];
        double inv = 1.0 / (sqrt(tt) + EPSD);
        g_inv_node_d[bn] = inv;
        g_inv_node_f[bn] = (float)inv;
    }
}

// =========================================================================
// K2: SPLIT-bf16 tensor-core GEMM (fp32-class accuracy):
//   sim = Hhi@Hhi^T + Hhi@Hlo^T + Hlo@Hhi^T   (lo*lo term negligible)
// 128x128 tiles, BK=32, 3-stage cp.async pipeline, symmetric (upper+mirror).
// Smem rows stride 80B: bank group (20*r mod 32) distinct for r=0..7 =>
// conflict-free ldmatrix without XOR swizzle.
// =========================================================================
#define SIM_STAGE_BYTES 40960          // 4 tiles * 128 rows * 80 B
#define SIM_TILE_BYTES  10240

__global__ void __launch_bounds__(256) k_sim_mma() {
    if (blockIdx.y > blockIdx.x) return;
    extern __shared__ __align__(16) unsigned char smraw[];
    const int t = threadIdx.x;
    const int lane = t & 31, warp = t >> 5;
    const int warp_m = warp >> 2, warp_n = warp & 3;
    const int bz = blockIdx.z;
    const int rowBase = blockIdx.y * 128, colBase = blockIdx.x * 128;
    const __nv_bfloat16* bhi = g_hbf + (size_t)bz * NN * PD;
    const __nv_bfloat16* blo = g_hlo + (size_t)bz * NN * PD;
    uint32_t s0 = (uint32_t)__cvta_generic_to_shared(smraw);

    float acc[4][4][4];
    #pragma unroll
    for (int i = 0; i < 4; i++)
        #pragma unroll
        for (int j = 0; j < 4; j++)
            #pragma unroll
            for (int q = 0; q < 4; q++) acc[i][j][q] = 0.f;

    // stage layout: [A_hi][A_lo][B_hi][B_lo], each 128 rows x 80 B
    auto issue = [&](int it, int buf) {
        int k0 = it * 32;
        uint32_t sb = s0 + buf * SIM_STAGE_BYTES;
        #pragma unroll
        for (int i = 0; i < 2; i++) {
            int u = t + 256 * i;
            int r = u >> 2, c = u & 3;
            uint32_t soff = r * 80 + c * 16;
            const __nv_bfloat16* ga = bhi + (size_t)(rowBase + r) * PD + k0 + c * 8;
            const __nv_bfloat16* gb = bhi + (size_t)(colBase + r) * PD + k0 + c * 8;
            const __nv_bfloat16* la = blo + (size_t)(rowBase + r) * PD + k0 + c * 8;
            const __nv_bfloat16* lb = blo + (size_t)(colBase + r) * PD + k0 + c * 8;
            cp16(sb + soff, ga);
            cp16(sb + SIM_TILE_BYTES + soff, la);
            cp16(sb + 2 * SIM_TILE_BYTES + soff, gb);
            cp16(sb + 3 * SIM_TILE_BYTES + soff, lb);
        }
        asm volatile("cp.async.commit_group;\n");
    };

    issue(0, 0);
    issue(1, 1);
    for (int it = 0; it < 126; it++) {
        if (it + 2 < 126) issue(it + 2, (it + 2) % 3);
        if (it < 124)      asm volatile("cp.async.wait_group 2;\n");
        else if (it == 124) asm volatile("cp.async.wait_group 1;\n");
        else               asm volatile("cp.async.wait_group 0;\n");
        __syncthreads();
        uint32_t sb = s0 + (it % 3) * SIM_STAGE_BYTES;
        uint32_t sAhi = sb, sAlo = sb + SIM_TILE_BYTES;
        uint32_t sBhi = sb + 2 * SIM_TILE_BYTES, sBlo = sb + 3 * SIM_TILE_BYTES;
        #pragma unroll
        for (int kk = 0; kk < 2; kk++) {
            uint32_t ahi[4][4], alo[4][4], bfh[4][2], bfl[4][2];
            #pragma unroll
            for (int mi = 0; mi < 4; mi++) {
                int row = warp_m * 64 + mi * 16 + ((lane >> 3) & 1) * 8 + (lane & 7);
                int ch = kk * 2 + (lane >> 4);
                uint32_t off = row * 80 + ch * 16;
                asm volatile("ldmatrix.sync.aligned.m8n8.x4.shared.b16 {%0,%1,%2,%3}, [%4];\n"
                    : "=r"(ahi[mi][0]), "=r"(ahi[mi][1]), "=r"(ahi[mi][2]), "=r"(ahi[mi][3])
                    : "r"(sAhi + off));
                asm volatile("ldmatrix.sync.aligned.m8n8.x4.shared.b16 {%0,%1,%2,%3}, [%4];\n"
                    : "=r"(alo[mi][0]), "=r"(alo[mi][1]), "=r"(alo[mi][2]), "=r"(alo[mi][3])
                    : "r"(sAlo + off));
            }
            #pragma unroll
            for (int call = 0; call < 2; call++) {
                int row = warp_n * 32 + call * 16 + ((lane >> 4) & 1) * 8 + (lane & 7);
                int ch = kk * 2 + ((lane >> 3) & 1);
                uint32_t off = row * 80 + ch * 16;
                uint32_t r0, r1, r2, r3;
                asm volatile("ldmatrix.sync.aligned.m8n8.x4.shared.b16 {%0,%1,%2,%3}, [%4];\n"
                    : "=r"(r0), "=r"(r1), "=r"(r2), "=r"(r3) : "r"(sBhi + off));
                bfh[call * 2][0] = r0; bfh[call * 2][1] = r1;
                bfh[call * 2 + 1][0] = r2; bfh[call * 2 + 1][1] = r3;
                asm volatile("ldmatrix.sync.aligned.m8n8.x4.shared.b16 {%0,%1,%2,%3}, [%4];\n"
                    : "=r"(r0), "=r"(r1), "=r"(r2), "=r"(r3) : "r"(sBlo + off));
                bfl[call * 2][0] = r0; bfl[call * 2][1] = r1;
                bfl[call * 2 + 1][0] = r2; bfl[call * 2 + 1][1] = r3;
            }
            #pragma unroll
            for (int mi = 0; mi < 4; mi++)
                #pragma unroll
                for (int ni = 0; ni < 4; ni++) {
                    asm volatile("mma.sync.aligned.m16n8k16.row.col.f32.bf16.bf16.f32 "
                        "{%0,%1,%2,%3}, {%4,%5,%6,%7}, {%8,%9}, {%0,%1,%2,%3};\n"
                        : "+f"(acc[mi][ni][0]), "+f"(acc[mi][ni][1]),
                          "+f"(acc[mi][ni][2]), "+f"(acc[mi][ni][3])
                        : "r"(ahi[mi][0]), "r"(ahi[mi][1]), "r"(ahi[mi][2]), "r"(ahi[mi][3]),
                          "r"(bfh[ni][0]), "r"(bfh[ni][1]));
                    asm volatile("mma.sync.aligned.m16n8k16.row.col.f32.bf16.bf16.f32 "
                        "{%0,%1,%2,%3}, {%4,%5,%6,%7}, {%8,%9}, {%0,%1,%2,%3};\n"
                        : "+f"(acc[mi][ni][0]), "+f"(acc[mi][ni][1]),
                          "+f"(acc[mi][ni][2]), "+f"(acc[mi][ni][3])
                        : "r"(ahi[mi][0]), "r"(ahi[mi][1]), "r"(ahi[mi][2]), "r"(ahi[mi][3]),
                          "r"(bfl[ni][0]), "r"(bfl[ni][1]));
                    asm volatile("mma.sync.aligned.m16n8k16.row.col.f32.bf16.bf16.f32 "
                        "{%0,%1,%2,%3}, {%4,%5,%6,%7}, {%8,%9}, {%0,%1,%2,%3};\n"
                        : "+f"(acc[mi][ni][0]), "+f"(acc[mi][ni][1]),
                          "+f"(acc[mi][ni][2]), "+f"(acc[mi][ni][3])
                        : "r"(alo[mi][0]), "r"(alo[mi][1]), "r"(alo[mi][2]), "r"(alo[mi][3]),
                          "r"(bfh[ni][0]), "r"(bfh[ni][1]));
                }
        }
        __syncthreads();
    }

    float* C = g_sim + (size_t)bz * NN * NN;
    const bool offdiag = (rowBase != colBase);
    #pragma unroll
    for (int mi = 0; mi < 4; mi++) {
        int r = rowBase + warp_m * 64 + mi * 16 + (lane >> 2);
        #pragma unroll
        for (int ni = 0; ni < 4; ni++) {
            int c = colBase + warp_n * 32 + ni * 8 + (lane & 3) * 2;
            *(float2*)(C + (size_t)r * NN + c) = make_float2(acc[mi][ni][0], acc[mi][ni][1]);
            *(float2*)(C + (size_t)(r + 8) * NN + c) = make_float2(acc[mi][ni][2], acc[mi][ni][3]);
            if (offdiag) {
                C[(size_t)c * NN + r]           = acc[mi][ni][0];
                C[(size_t)(c + 1) * NN + r]     = acc[mi][ni][1];
                C[(size_t)c * NN + r + 8]       = acc[mi][ni][2];
                C[(size_t)(c + 1) * NN + r + 8] = acc[mi][ni][3];
            }
        }
    }
}

// =========================================================================
// K3: top-12 node candidates + delta-gated exact re-rank -> g_node (top-8).
// Prepass (split GEMM) error ~1.5e-7; pairs with gap < 1e-5 are resolved by
// exact compensated dots (rare).  Results identical to full exact re-rank.
// =========================================================================
__global__ __launch_bounds__(256) void k_topk_node(const float* __restrict__ h) {
    int bn = blockIdx.x;
    int b = bn >> 10, n = bn & 1023;
    __shared__ float vals[NN];
    __shared__ float rv[256];
    __shared__ int   ri[256];
    __shared__ float selv[KCAND];
    __shared__ int   scand[KCAND];
    __shared__ double exd[KCAND];
    __shared__ int   s_mask;
    int t = threadIdx.x, warp = t >> 5, lane = t & 31;
    float invn = g_inv_node_f[bn];
    const float* row = g_sim + (size_t)b * NN * NN + (size_t)n * NN;
    for (int m = t; m < NN; m += 256) {
        vals[m] = (m == n) ? 0.f : row[m] * invn * g_inv_node_f[b * NN + m];
    }
    __syncthreads();
    for (int k = 0; k < KCAND; k++) {
        float bv = NEG_INF; int bi = 0;
        #pragma unroll
        for (int j = 0; j < 4; j++) {
            int m = t + j * 256;
            float v = vals[m];
            if (v > bv) { bv = v; bi = m; }
        }
        rv[t] = bv; ri[t] = bi;
        __syncthreads();
        if (t < 32) {
            float v = rv[t]; int i = ri[t];
            #pragma unroll
            for (int j = 1; j < 8; j++) {
                float v2 = rv[t + j * 32]; int i2 = ri[t + j * 32];
                if (v2 > v || (v2 == v && i2 < i)) { v = v2; i = i2; }
            }
            #pragma unroll
            for (int o = 16; o; o >>= 1) {
                float v2 = __shfl_xor_sync(0xffffffffu, v, o);
                int   i2 = __shfl_xor_sync(0xffffffffu, i, o);
                if (v2 > v || (v2 == v && i2 < i)) { v = v2; i = i2; }
            }
            if (t == 0) {
                selv[k] = v;
                scand[k] = i;
                vals[i] = NEG_INF;
            }
        }
        __syncthreads();
    }

    // ---- ambiguity clusters ----
    if (t == 0) {
        int mask = 0;
        int i = 0;
        while (i < KCAND - 1) {
            if (selv[i] - selv[i + 1] < DELTA_NODE) {
                int jx = i;
                while (jx < KCAND - 1 && selv[jx] - selv[jx + 1] < DELTA_NODE) jx++;
                if (i <= 7) {
                    for (int q = i; q <= jx; q++) mask |= 1 << q;
                }
                i = jx + 1;
            } else i++;
        }
        s_mask = mask;
    }
    __syncthreads();
    int mask = s_mask;

    if (mask) {
        // exact dots for flagged candidates: warp per candidate
        const float4* q4 = (const float4*)(h + (size_t)bn * PD);
        for (int c = warp; c < KCAND; c += 8) {
            if (!((mask >> c) & 1)) continue;
            int m = scand[c];
            const float4* f4 = (const float4*)(h + (size_t)(b * NN + m) * PD);
            float hx = 0.f, lx = 0.f, hy = 0.f, ly = 0.f;
            float hz = 0.f, lz = 0.f, hw = 0.f, lw = 0.f;
            #pragma unroll 4
            for (int j = 0; j < 31; j++) {
                int i4 = j * 32 + lane;
                float4 a = q4[i4];
                float4 cc = f4[i4];
                dot2_step(a.x, cc.x, hx, lx);
                dot2_step(a.y, cc.y, hy, ly);
                dot2_step(a.z, cc.z, hz, lz);
                dot2_step(a.w, cc.w, hw, lw);
            }
            if (lane < 16) {
                int i4 = 992 + lane;
                float4 a = q4[i4];
                float4 cc = f4[i4];
                dot2_step(a.x, cc.x, hx, lx);
                dot2_step(a.y, cc.y, hy, ly);
                dot2_step(a.z, cc.z, hz, lz);
                dot2_step(a.w, cc.w, hw, lw);
            }
            double v = ((double)hx + lx) + ((double)hy + ly) +
                       ((double)hz + lz) + ((double)hw + lw);
            #pragma unroll
            for (int o = 16; o; o >>= 1) v += __shfl_xor_sync(0xffffffffu, v, o);
            if (lane == 0)
                exd[c] = v * g_inv_node_d[bn] * g_inv_node_d[b * NN + m];
        }
        __syncthreads();
    }

    if (t == 0) {
        if (!mask) {
            #pragma unroll
            for (int k = 0; k < KNODE; k++) g_node[bn * KNODE + k] = scand[k];
        } else {
            double vv[KCAND];
            #pragma unroll
            for (int j = 0; j < KCAND; j++)
                vv[j] = ((mask >> j) & 1) ? exd[j] : (double)selv[j];
            unsigned used = 0;
            for (int k = 0; k < KNODE; k++) {
                int best = -1;
                for (int j = 0; j < KCAND; j++) {
                    if (used & (1u << j)) continue;
                    if (best < 0 || vv[j] > vv[best] ||
                        (vv[j] == vv[best] && scand[j] < scand[best])) best = j;
                }
                used |= (1u << best);
                g_node[bn * KNODE + k] = scand[best];
            }
        }
    }
}

// =========================================================================
// K4: token sims (fp32 prepass).  One block per (bn, kn).
// =========================================================================
__global__ __launch_bounds__(128) void k_tsim(const float* __restrict__ h) {
    __shared__ float sR[PP * 97];
    __shared__ float sq[DD];

    int bk = blockIdx.x;
    int bn = bk >> 3, kn = bk & 7;
    int b = bn >> 10;
    int t = threadIdx.x;

    int m = g_node[bn * KNODE + kn];
    const float4* row4 = (const float4*)(h + (size_t)(b * NN + m) * PD);
    for (int i4 = t; i4 < PD / 4; i4 += 128) {
        int p = i4 / 24, d4 = i4 - p * 24;
        float4 v = row4[i4];
        float* dst = &sR[p * 97 + d4 * 4];
        dst[0] = v.x; dst[1] = v.y; dst[2] = v.z; dst[3] = v.w;
    }
    if (t < DD / 4) {
        float4 v = ((const float4*)(h + ((size_t)bn * PP + (PP - 1)) * DD))[t];
        float* dst = &sq[t * 4];
        dst[0] = v.x; dst[1] = v.y; dst[2] = v.z; dst[3] = v.w;
    }
    __syncthreads();

    if (t < PP) {
        const float* r = &sR[t * 97];
        float a0 = 0.f, a1 = 0.f, a2 = 0.f, a3 = 0.f;
        #pragma unroll 8
        for (int d = 0; d < DD; d += 4) {
            a0 = fmaf(r[d],     sq[d],     a0);
            a1 = fmaf(r[d + 1], sq[d + 1], a1);
            a2 = fmaf(r[d + 2], sq[d + 2], a2);
            a3 = fmaf(r[d + 3], sq[d + 3], a3);
        }
        double v = (double)((a0 + a1) + (a2 + a3));
        v = v * g_inv_tok_d[bn * PP + PP - 1] * g_inv_tok_d[(b * NN + m) * PP + t];
        g_tsim[(size_t)bn * (KNODE * PP) + kn * PP + t] = (float)v;
    }
}

// =========================================================================
// K5: token select — rank-count top-12, exact dot2 re-rank, top-8 -> g_sel.
// =========================================================================
__global__ __launch_bounds__(128) void k_tsel(const float* __restrict__ h) {
    __shared__ __align__(16) float ss[KNODE * PP];
    __shared__ float sq[DD];
    __shared__ int    tcand[KTC];
    __shared__ double texd[KTC];
    __shared__ int    snode[KNODE];

    int bn = blockIdx.x;
    int b = bn >> 10;
    int t = threadIdx.x, warp = t >> 5, lane = t & 31;

    const float4* ts4 = (const float4*)(g_tsim + (size_t)bn * (KNODE * PP));
    if (t < (KNODE * PP) / 4) ((float4*)ss)[t] = ts4[t];
    if (t < DD) sq[t] = h[((size_t)bn * PP + (PP - 1)) * DD + t];
    if (t < KNODE) snode[t] = g_node[bn * KNODE + t];
    __syncthreads();

    for (int c = t; c < KNODE * PP; c += 128) {
        float vt = ss[c];
        const float4* s4 = (const float4*)ss;
        int rank = 0;
        #pragma unroll 4
        for (int j4 = 0; j4 < (KNODE * PP) / 4; j4++) {
            float4 vv = s4[j4];
            int j = j4 * 4;
            rank += (vv.x > vt || (vv.x == vt && (j + 0) < c));
            rank += (vv.y > vt || (vv.y == vt && (j + 1) < c));
            rank += (vv.z > vt || (vv.z == vt && (j + 2) < c));
            rank += (vv.w > vt || (vv.w == vt && (j + 3) < c));
        }
        if (rank < KTC) tcand[rank] = c;
    }
    __syncthreads();

    for (int cc = warp; cc < KTC; cc += 4) {
        int c = tcand[cc];
        int kn = c / PP, p = c - kn * PP;
        int m = snode[kn];
        const float* tp = h + (((size_t)(b * NN + m)) * PP + p) * (size_t)DD;
        float hi = 0.f, lo = 0.f;
        dot2_step(tp[lane],      sq[lane],      hi, lo);
        dot2_step(tp[lane + 32], sq[lane + 32], hi, lo);
        dot2_step(tp[lane + 64], sq[lane + 64], hi, lo);
        double v = (double)hi + (double)lo;
        #pragma unroll
        for (int o = 16; o; o >>= 1) v += __shfl_xor_sync(0xffffffffu, v, o);
        if (lane == 0)
            texd[cc] = v * g_inv_tok_d[bn * PP + PP - 1] *
                       g_inv_tok_d[(b * NN + m) * PP + p];
    }
    __syncthreads();

    if (t == 0) {
        unsigned used = 0;
        for (int k = 0; k < KTOK; k++) {
            int best = -1;
            for (int j = 0; j < KTC; j++) {
                if (used & (1u << j)) continue;
                if (best < 0 || texd[j] > texd[best] ||
                    (texd[j] == texd[best] && tcand[j] < tcand[best])) best = j;
            }
            used |= (1u << best);
            int c = tcand[best];
            int kn = c / PP, p = c - kn * PP;
            g_sel[bn * KTOK + k] = snode[kn] * 64 + p;
        }
    }
}

// =========================================================================
// K6: sk linear — gather 64 selected tokens/block, x @ W^T + b + nt.
// =========================================================================
__global__ __launch_bounds__(256) void k_sklin(const float* __restrict__ h,
                                               const float* __restrict__ W,
                                               const float* __restrict__ bias,
                                               const float* __restrict__ ntok,
                                               float* __restrict__ out) {
    __shared__ __align__(16) float sXT[DD * 68];
    __shared__ __align__(16) float sWT[DD * 98];
    __shared__ size_t rowoff[64];

    int r0 = blockIdx.x * 64;
    int t = threadIdx.x;

    if (t < 64) {
        int rr = r0 + t;
        int bn = rr >> 3;
        int b = bn >> 10;
        int s = g_sel[bn * KTOK + (rr & 7)];
        int m = s >> 6, p = s & 63;
        rowoff[t] = (((size_t)(b * NN + m)) * PP + p) * (size_t)DD;
    }
    __syncthreads();

    for (int i = t; i < 64 * DD; i += 256) {
        int r = i / DD, d = i - r * DD;
        sXT[d * 68 + r] = h[rowoff[r] + d];
    }
    for (int i = t; i < DD * DD; i += 256) {
        int e = i / DD, d = i - e * DD;
        sWT[d * 98 + e] = W[i];
    }
    __syncthreads();

    float nt = ntok[0];
    int tx = t & 15, ty = t >> 4;
    unsigned long long acc[4][3];
    #pragma unroll
    for (int i = 0; i < 4; i++)
        #pragma unroll
        for (int j = 0; j < 3; j++)
            acc[i][j] = pk2(bias[tx * 6 + 2 * j] + nt, bias[tx * 6 + 2 * j + 1] + nt);

    #pragma unroll 4
    for (int d = 0; d < DD; d++) {
        float4 xv = *(const float4*)(sXT + d * 68 + ty * 4);
        const unsigned long long* wp = (const unsigned long long*)(sWT + d * 98 + tx * 6);
        unsigned long long b0 = wp[0], b1 = wp[1], b2 = wp[2];
        float x[4] = {xv.x, xv.y, xv.z, xv.w};
        #pragma unroll
        for (int i = 0; i < 4; i++) {
            unsigned long long a = pk2(x[i], x[i]);
            fma2(acc[i][0], a, b0);
            fma2(acc[i][1], a, b1);
            fma2(acc[i][2], a, b2);
        }
    }

    #pragma unroll
    for (int i = 0; i < 4; i++) {
        int rr = r0 + ty * 4 + i;
        int bn = rr >> 3, k = rr & 7;
        float* orow = out + (((size_t)bn) * POUT + PP + k) * (size_t)DD + tx * 6;
        #pragma unroll
        for (int j = 0; j < 3; j++) {
            float lo, hi;
            upk2(acc[i][j], lo, hi);
            orow[2 * j] = lo;
            orow[2 * j + 1] = hi;
        }
    }
}

// =========================================================================
// K7: hf = h @ W^T + b -> out[:, :, 0:42, :].  f32x2 packed FFMA.
// =========================================================================
__global__ __launch_bounds__(256) void k_hf(const float* __restrict__ h,
                                            const float* __restrict__ W,
                                            const float* __restrict__ bias,
                                            float* __restrict__ out) {
    extern __shared__ __align__(16) float dyn[];
    float* sXT = dyn;                 // [DD][68]
    float* sWT = dyn + DD * 68;       // [DD][98]

    int r0 = blockIdx.x * 64;
    int t = threadIdx.x;

    const float* Xbase = h + (size_t)r0 * DD;
    for (int i = t; i < 64 * DD; i += 256) {
        int r = i / DD, d = i - r * DD;
        sXT[d * 68 + r] = Xbase[i];
    }
    for (int i = t; i < DD * DD; i += 256) {
        int e = i / DD, d = i - e * DD;
        sWT[d * 98 + e] = W[i];
    }
    __syncthreads();

    int tx = t & 15, ty = t >> 4;
    unsigned long long acc[4][3];
    #pragma unroll
    for (int i = 0; i < 4; i++)
        #pragma unroll
        for (int j = 0; j < 3; j++)
            acc[i][j] = pk2(bias[tx * 6 + 2 * j], bias[tx * 6 + 2 * j + 1]);

    #pragma unroll 4
    for (int d = 0; d < DD; d++) {
        float4 xv = *(const float4*)(sXT + d * 68 + ty * 4);
        const unsigned long long* wp = (const unsigned long long*)(sWT + d * 98 + tx * 6);
        unsigned long long b0 = wp[0], b1 = wp[1], b2 = wp[2];
        float x[4] = {xv.x, xv.y, xv.z, xv.w};
        #pragma unroll
        for (int i = 0; i < 4; i++) {
            unsigned long long a = pk2(x[i], x[i]);
            fma2(acc[i][0], a, b0);
            fma2(acc[i][1], a, b1);
            fma2(acc[i][2], a, b2);
        }
    }

    #pragma unroll
    for (int i = 0; i < 4; i++) {
        int r = r0 + ty * 4 + i;
        int bn = r / PP, p = r - bn * PP;
        float* orow = out + (((size_t)bn) * POUT + p) * (size_t)DD + tx * 6;
        #pragma unroll
        for (int j = 0; j < 3; j++) {
            float lo, hi;
            upk2(acc[i][j], lo, hi);
            orow[2 * j] = lo;
            orow[2 * j + 1] = hi;
        }
    }
}

// =========================================================================
extern "C" void kernel_launch(void* const* d_in, const int* in_sizes, int n_in,
                              void* d_out, int out_size) {
    const float* h    = (const float*)d_in[0];
    const float* W    = (const float*)d_in[1];
    const float* bias = (const float*)d_in[2];
    const float* ntok = (const float*)d_in[3];
    float* out = (float*)d_out;

    k_convnorm<<<BB * NN, 128>>>(h);                                 // 1

    cudaFuncSetAttribute(k_sim_mma, cudaFuncAttributeMaxDynamicSharedMemorySize,
                         3 * SIM_STAGE_BYTES);
    dim3 g2(NN / 128, NN / 128, BB);
    k_sim_mma<<<g2, 256, 3 * SIM_STAGE_BYTES>>>();                   // 2

    k_topk_node<<<BB * NN, 256>>>(h);                                // 3

    k_tsim<<<BB * NN * KNODE, 128>>>(h);                             // 4  <- profiled slot

    k_tsel<<<BB * NN, 128>>>(h);                                     // 5

    k_sklin<<<(BB * NN * KTOK) / 64, 256>>>(h, W, bias, ntok, out);  // 6

    size_t hf_smem = (size_t)(DD * 68 + DD * 98) * sizeof(float);
    cudaFuncSetAttribute(k_hf, cudaFuncAttributeMaxDynamicSharedMemorySize, (int)hf_smem);
    k_hf<<<(BB * NN * PP) / 64, 256, hf_smem>>>(h, W, bias, out);    // 7
}

// round 15
// speedup vs baseline: 1.3264x; 1.0152x over previous
#include <cuda_runtime.h>
#include <cuda_bf16.h>
#include <cstdint>
#include <math.h>

#define BB 4
#define NN 1024
#define PP 42
#define DD 96
#define PD 4032          // PP*DD
#define KNODE 8
#define KCAND 12         // node prepass candidates
#define KTOK 8
#define KTC 12           // token prepass candidates
#define POUT 50          // PP + KTOK
#define EPSD 1e-7
#define DELTA_NODE 1e-5f // ambiguity gate (prepass err ~1.5e-7 rms)

#define NEG_INF __int_as_float(0xff800000)

// ---------------- scratch (device globals; no allocation) ----------------
__device__ float  g_sim[BB * NN * NN];
__device__ __align__(16) __nv_bfloat16 g_hbf[BB * NN * PD];   // hi part
__device__ __align__(16) __nv_bfloat16 g_hlo[BB * NN * PD];   // lo part
__device__ double g_inv_node_d[BB * NN];
__device__ float  g_inv_node_f[BB * NN];
__device__ double g_inv_tok_d[BB * NN * PP];
__device__ int    g_node[BB * NN * KNODE];
__device__ __align__(16) float g_tsim[BB * NN * KNODE * PP];  // 336 per bn
__device__ int    g_sel[BB * NN * KTOK];      // selected tokens: m*64 + p

// ---------------- compensated arithmetic helpers --------------------------
__device__ __forceinline__ void two_sum(float a, float b, float& s, float& e) {
    s = a + b;
    float z = s - a;
    e = (a - (s - z)) + (b - z);
}
__device__ __forceinline__ void dot2_step(float a, float b, float& hi, float& lo) {
    float p = a * b;
    float ep = fmaf(a, b, -p);
    float s, e;
    two_sum(hi, p, s, e);
    hi = s;
    lo += e + ep;
}

__device__ __forceinline__ void cp16(uint32_t s, const void* g) {
    asm volatile("cp.async.cg.shared.global [%0], [%1], 16;\n" :: "r"(s), "l"(g));
}

// ---------------- packed f32x2 helpers (Blackwell FFMA2) ------------------
__device__ __forceinline__ unsigned long long pk2(float lo, float hi) {
    unsigned long long r;
    asm("mov.b64 %0, {%1, %2};" : "=l"(r) : "f"(lo), "f"(hi));
    return r;
}
__device__ __forceinline__ void fma2(unsigned long long& d,
                                     unsigned long long a, unsigned long long b) {
    asm("fma.rn.f32x2 %0, %1, %2, %0;" : "+l"(d) : "l"(a), "l"(b));
}
__device__ __forceinline__ void upk2(unsigned long long v, float& lo, float& hi) {
    asm("mov.b64 {%0, %1}, %2;" : "=f"(lo), "=f"(hi) : "l"(v));
}

// =========================================================================
// K0: bf16 SPLIT conversion (hi+lo).  Pure streaming kernel.
// =========================================================================
__global__ __launch_bounds__(256) void k_conv(const float* __restrict__ h) {
    size_t i = ((size_t)blockIdx.x * 256 + threadIdx.x);
    float4 v = ((const float4*)h)[i];
    __nv_bfloat16 h0 = __float2bfloat16_rn(v.x);
    __nv_bfloat16 h1 = __float2bfloat16_rn(v.y);
    __nv_bfloat16 h2 = __float2bfloat16_rn(v.z);
    __nv_bfloat16 h3 = __float2bfloat16_rn(v.w);
    __nv_bfloat162 hp0; hp0.x = h0; hp0.y = h1;
    __nv_bfloat162 hp1; hp1.x = h2; hp1.y = h3;
    uint2 pkh;
    pkh.x = *(uint32_t*)&hp0;
    pkh.y = *(uint32_t*)&hp1;
    ((uint2*)g_hbf)[i] = pkh;
    __nv_bfloat162 lp0, lp1;
    lp0.x = __float2bfloat16_rn(v.x - __bfloat162float(h0));
    lp0.y = __float2bfloat16_rn(v.y - __bfloat162float(h1));
    lp1.x = __float2bfloat16_rn(v.z - __bfloat162float(h2));
    lp1.y = __float2bfloat16_rn(v.w - __bfloat162float(h3));
    uint2 pkl;
    pkl.x = *(uint32_t*)&lp0;
    pkl.y = *(uint32_t*)&lp1;
    ((uint2*)g_hlo)[i] = pkl;
}

// =========================================================================
// K1: exact token/node norms (compensated fp32 -> fp64).
// =========================================================================
__global__ __launch_bounds__(128) void k_norms(const float* __restrict__ h) {
    int bn = blockIdx.x;
    const float* base = h + (size_t)bn * PD;
    __shared__ double s_node[4];
    int t = threadIdx.x, warp = t >> 5, lane = t & 31;

    double nodesum = 0.0;
    for (int p = warp; p < PP; p += 4) {
        const float* tp = base + p * DD;
        float hi = 0.f, lo = 0.f;
        float v0 = tp[lane], v1 = tp[lane + 32], v2 = tp[lane + 64];
        dot2_step(v0, v0, hi, lo);
        dot2_step(v1, v1, hi, lo);
        dot2_step(v2, v2, hi, lo);
        double s = (double)hi + (double)lo;
        #pragma unroll
        for (int o = 16; o; o >>= 1) s += __shfl_xor_sync(0xffffffffu, s, o);
        if (lane == 0) g_inv_tok_d[bn * PP + p] = 1.0 / (sqrt(s) + EPSD);
        nodesum += s;
    }
    if (lane == 0) s_node[warp] = nodesum;
    __syncthreads();
    if (t == 0) {
        double tt = s_node[0] + s_node[1] + s_node[2] + s_node[3];
        double inv = 1.0 / (sqrt(tt) + EPSD);
        g_inv_node_d[bn] = inv;
        g_inv_node_f[bn] = (float)inv;
    }
}

// =========================================================================
// K2: SPLIT-bf16 tensor-core GEMM (fp32-class accuracy):
//   sim = Hhi@Hhi^T + Hhi@Hlo^T + Hlo@Hhi^T
// 128x128 tiles, BK=32, 3-stage cp.async pipeline, symmetric (upper+mirror).
// =========================================================================
#define SIM_STAGE_BYTES 40960          // 4 tiles * 128 rows * 80 B
#define SIM_TILE_BYTES  10240

__global__ void __launch_bounds__(256) k_sim_mma() {
    if (blockIdx.y > blockIdx.x) return;
    extern __shared__ __align__(16) unsigned char smraw[];
    const int t = threadIdx.x;
    const int lane = t & 31, warp = t >> 5;
    const int warp_m = warp >> 2, warp_n = warp & 3;
    const int bz = blockIdx.z;
    const int rowBase = blockIdx.y * 128, colBase = blockIdx.x * 128;
    const __nv_bfloat16* bhi = g_hbf + (size_t)bz * NN * PD;
    const __nv_bfloat16* blo = g_hlo + (size_t)bz * NN * PD;
    uint32_t s0 = (uint32_t)__cvta_generic_to_shared(smraw);

    float acc[4][4][4];
    #pragma unroll
    for (int i = 0; i < 4; i++)
        #pragma unroll
        for (int j = 0; j < 4; j++)
            #pragma unroll
            for (int q = 0; q < 4; q++) acc[i][j][q] = 0.f;

    auto issue = [&](int it, int buf) {
        int k0 = it * 32;
        uint32_t sb = s0 + buf * SIM_STAGE_BYTES;
        #pragma unroll
        for (int i = 0; i < 2; i++) {
            int u = t + 256 * i;
            int r = u >> 2, c = u & 3;
            uint32_t soff = r * 80 + c * 16;
            const __nv_bfloat16* ga = bhi + (size_t)(rowBase + r) * PD + k0 + c * 8;
            const __nv_bfloat16* gb = bhi + (size_t)(colBase + r) * PD + k0 + c * 8;
            const __nv_bfloat16* la = blo + (size_t)(rowBase + r) * PD + k0 + c * 8;
            const __nv_bfloat16* lb = blo + (size_t)(colBase + r) * PD + k0 + c * 8;
            cp16(sb + soff, ga);
            cp16(sb + SIM_TILE_BYTES + soff, la);
            cp16(sb + 2 * SIM_TILE_BYTES + soff, gb);
            cp16(sb + 3 * SIM_TILE_BYTES + soff, lb);
        }
        asm volatile("cp.async.commit_group;\n");
    };

    issue(0, 0);
    issue(1, 1);
    for (int it = 0; it < 126; it++) {
        if (it + 2 < 126) issue(it + 2, (it + 2) % 3);
        if (it < 124)      asm volatile("cp.async.wait_group 2;\n");
        else if (it == 124) asm volatile("cp.async.wait_group 1;\n");
        else               asm volatile("cp.async.wait_group 0;\n");
        __syncthreads();
        uint32_t sb = s0 + (it % 3) * SIM_STAGE_BYTES;
        uint32_t sAhi = sb, sAlo = sb + SIM_TILE_BYTES;
        uint32_t sBhi = sb + 2 * SIM_TILE_BYTES, sBlo = sb + 3 * SIM_TILE_BYTES;
        #pragma unroll
        for (int kk = 0; kk < 2; kk++) {
            uint32_t ahi[4][4], alo[4][4], bfh[4][2], bfl[4][2];
            #pragma unroll
            for (int mi = 0; mi < 4; mi++) {
                int row = warp_m * 64 + mi * 16 + ((lane >> 3) & 1) * 8 + (lane & 7);
                int ch = kk * 2 + (lane >> 4);
                uint32_t off = row * 80 + ch * 16;
                asm volatile("ldmatrix.sync.aligned.m8n8.x4.shared.b16 {%0,%1,%2,%3}, [%4];\n"
                    : "=r"(ahi[mi][0]), "=r"(ahi[mi][1]), "=r"(ahi[mi][2]), "=r"(ahi[mi][3])
                    : "r"(sAhi + off));
                asm volatile("ldmatrix.sync.aligned.m8n8.x4.shared.b16 {%0,%1,%2,%3}, [%4];\n"
                    : "=r"(alo[mi][0]), "=r"(alo[mi][1]), "=r"(alo[mi][2]), "=r"(alo[mi][3])
                    : "r"(sAlo + off));
            }
            #pragma unroll
            for (int call = 0; call < 2; call++) {
                int row = warp_n * 32 + call * 16 + ((lane >> 4) & 1) * 8 + (lane & 7);
                int ch = kk * 2 + ((lane >> 3) & 1);
                uint32_t off = row * 80 + ch * 16;
                uint32_t r0, r1, r2, r3;
                asm volatile("ldmatrix.sync.aligned.m8n8.x4.shared.b16 {%0,%1,%2,%3}, [%4];\n"
                    : "=r"(r0), "=r"(r1), "=r"(r2), "=r"(r3) : "r"(sBhi + off));
                bfh[call * 2][0] = r0; bfh[call * 2][1] = r1;
                bfh[call * 2 + 1][0] = r2; bfh[call * 2 + 1][1] = r3;
                asm volatile("ldmatrix.sync.aligned.m8n8.x4.shared.b16 {%0,%1,%2,%3}, [%4];\n"
                    : "=r"(r0), "=r"(r1), "=r"(r2), "=r"(r3) : "r"(sBlo + off));
                bfl[call * 2][0] = r0; bfl[call * 2][1] = r1;
                bfl[call * 2 + 1][0] = r2; bfl[call * 2 + 1][1] = r3;
            }
            #pragma unroll
            for (int mi = 0; mi < 4; mi++)
                #pragma unroll
                for (int ni = 0; ni < 4; ni++) {
                    asm volatile("mma.sync.aligned.m16n8k16.row.col.f32.bf16.bf16.f32 "
                        "{%0,%1,%2,%3}, {%4,%5,%6,%7}, {%8,%9}, {%0,%1,%2,%3};\n"
                        : "+f"(acc[mi][ni][0]), "+f"(acc[mi][ni][1]),
                          "+f"(acc[mi][ni][2]), "+f"(acc[mi][ni][3])
                        : "r"(ahi[mi][0]), "r"(ahi[mi][1]), "r"(ahi[mi][2]), "r"(ahi[mi][3]),
                          "r"(bfh[ni][0]), "r"(bfh[ni][1]));
                    asm volatile("mma.sync.aligned.m16n8k16.row.col.f32.bf16.bf16.f32 "
                        "{%0,%1,%2,%3}, {%4,%5,%6,%7}, {%8,%9}, {%0,%1,%2,%3};\n"
                        : "+f"(acc[mi][ni][0]), "+f"(acc[mi][ni][1]),
                          "+f"(acc[mi][ni][2]), "+f"(acc[mi][ni][3])
                        : "r"(ahi[mi][0]), "r"(ahi[mi][1]), "r"(ahi[mi][2]), "r"(ahi[mi][3]),
                          "r"(bfl[ni][0]), "r"(bfl[ni][1]));
                    asm volatile("mma.sync.aligned.m16n8k16.row.col.f32.bf16.bf16.f32 "
                        "{%0,%1,%2,%3}, {%4,%5,%6,%7}, {%8,%9}, {%0,%1,%2,%3};\n"
                        : "+f"(acc[mi][ni][0]), "+f"(acc[mi][ni][1]),
                          "+f"(acc[mi][ni][2]), "+f"(acc[mi][ni][3])
                        : "r"(alo[mi][0]), "r"(alo[mi][1]), "r"(alo[mi][2]), "r"(alo[mi][3]),
                          "r"(bfh[ni][0]), "r"(bfh[ni][1]));
                }
        }
        __syncthreads();
    }

    float* C = g_sim + (size_t)bz * NN * NN;
    const bool offdiag = (rowBase != colBase);
    #pragma unroll
    for (int mi = 0; mi < 4; mi++) {
        int r = rowBase + warp_m * 64 + mi * 16 + (lane >> 2);
        #pragma unroll
        for (int ni = 0; ni < 4; ni++) {
            int c = colBase + warp_n * 32 + ni * 8 + (lane & 3) * 2;
            *(float2*)(C + (size_t)r * NN + c) = make_float2(acc[mi][ni][0], acc[mi][ni][1]);
            *(float2*)(C + (size_t)(r + 8) * NN + c) = make_float2(acc[mi][ni][2], acc[mi][ni][3]);
            if (offdiag) {
                C[(size_t)c * NN + r]           = acc[mi][ni][0];
                C[(size_t)(c + 1) * NN + r]     = acc[mi][ni][1];
                C[(size_t)c * NN + r + 8]       = acc[mi][ni][2];
                C[(size_t)(c + 1) * NN + r + 8] = acc[mi][ni][3];
            }
        }
    }
}

// =========================================================================
// K3: top-12 node candidates + delta-gated exact re-rank -> g_node (top-8).
// =========================================================================
__global__ __launch_bounds__(256) void k_topk_node(const float* __restrict__ h) {
    int bn = blockIdx.x;
    int b = bn >> 10, n = bn & 1023;
    __shared__ float vals[NN];
    __shared__ float rv[256];
    __shared__ int   ri[256];
    __shared__ float selv[KCAND];
    __shared__ int   scand[KCAND];
    __shared__ double exd[KCAND];
    __shared__ int   s_mask;
    int t = threadIdx.x, warp = t >> 5, lane = t & 31;
    float invn = g_inv_node_f[bn];
    const float* row = g_sim + (size_t)b * NN * NN + (size_t)n * NN;
    for (int m = t; m < NN; m += 256) {
        vals[m] = (m == n) ? 0.f : row[m] * invn * g_inv_node_f[b * NN + m];
    }
    __syncthreads();
    for (int k = 0; k < KCAND; k++) {
        float bv = NEG_INF; int bi = 0;
        #pragma unroll
        for (int j = 0; j < 4; j++) {
            int m = t + j * 256;
            float v = vals[m];
            if (v > bv) { bv = v; bi = m; }
        }
        rv[t] = bv; ri[t] = bi;
        __syncthreads();
        if (t < 32) {
            float v = rv[t]; int i = ri[t];
            #pragma unroll
            for (int j = 1; j < 8; j++) {
                float v2 = rv[t + j * 32]; int i2 = ri[t + j * 32];
                if (v2 > v || (v2 == v && i2 < i)) { v = v2; i = i2; }
            }
            #pragma unroll
            for (int o = 16; o; o >>= 1) {
                float v2 = __shfl_xor_sync(0xffffffffu, v, o);
                int   i2 = __shfl_xor_sync(0xffffffffu, i, o);
                if (v2 > v || (v2 == v && i2 < i)) { v = v2; i = i2; }
            }
            if (t == 0) {
                selv[k] = v;
                scand[k] = i;
                vals[i] = NEG_INF;
            }
        }
        __syncthreads();
    }

    if (t == 0) {
        int mask = 0;
        int i = 0;
        while (i < KCAND - 1) {
            if (selv[i] - selv[i + 1] < DELTA_NODE) {
                int jx = i;
                while (jx < KCAND - 1 && selv[jx] - selv[jx + 1] < DELTA_NODE) jx++;
                if (i <= 7) {
                    for (int q = i; q <= jx; q++) mask |= 1 << q;
                }
                i = jx + 1;
            } else i++;
        }
        s_mask = mask;
    }
    __syncthreads();
    int mask = s_mask;

    if (mask) {
        const float4* q4 = (const float4*)(h + (size_t)bn * PD);
        for (int c = warp; c < KCAND; c += 8) {
            if (!((mask >> c) & 1)) continue;
            int m = scand[c];
            const float4* f4 = (const float4*)(h + (size_t)(b * NN + m) * PD);
            float hx = 0.f, lx = 0.f, hy = 0.f, ly = 0.f;
            float hz = 0.f, lz = 0.f, hw = 0.f, lw = 0.f;
            #pragma unroll 4
            for (int j = 0; j < 31; j++) {
                int i4 = j * 32 + lane;
                float4 a = q4[i4];
                float4 cc = f4[i4];
                dot2_step(a.x, cc.x, hx, lx);
                dot2_step(a.y, cc.y, hy, ly);
                dot2_step(a.z, cc.z, hz, lz);
                dot2_step(a.w, cc.w, hw, lw);
            }
            if (lane < 16) {
                int i4 = 992 + lane;
                float4 a = q4[i4];
                float4 cc = f4[i4];
                dot2_step(a.x, cc.x, hx, lx);
                dot2_step(a.y, cc.y, hy, ly);
                dot2_step(a.z, cc.z, hz, lz);
                dot2_step(a.w, cc.w, hw, lw);
            }
            double v = ((double)hx + lx) + ((double)hy + ly) +
                       ((double)hz + lz) + ((double)hw + lw);
            #pragma unroll
            for (int o = 16; o; o >>= 1) v += __shfl_xor_sync(0xffffffffu, v, o);
            if (lane == 0)
                exd[c] = v * g_inv_node_d[bn] * g_inv_node_d[b * NN + m];
        }
        __syncthreads();
    }

    if (t == 0) {
        if (!mask) {
            #pragma unroll
            for (int k = 0; k < KNODE; k++) g_node[bn * KNODE + k] = scand[k];
        } else {
            double vv[KCAND];
            #pragma unroll
            for (int j = 0; j < KCAND; j++)
                vv[j] = ((mask >> j) & 1) ? exd[j] : (double)selv[j];
            unsigned used = 0;
            for (int k = 0; k < KNODE; k++) {
                int best = -1;
                for (int j = 0; j < KCAND; j++) {
                    if (used & (1u << j)) continue;
                    if (best < 0 || vv[j] > vv[best] ||
                        (vv[j] == vv[best] && scand[j] < scand[best])) best = j;
                }
                used |= (1u << best);
                g_node[bn * KNODE + k] = scand[best];
            }
        }
    }
}

// =========================================================================
// K4: token sims (fp32 prepass).  One block per (bn, kn).  float4 smem
// layout, stride 25 float4 (25 mod 8 == 1 -> conflict-free LDS.128).
// Arithmetic order identical to previous scalar version.
// =========================================================================
__global__ __launch_bounds__(128) void k_tsim(const float* __restrict__ h) {
    __shared__ float4 sR4[PP * 25];              // row p at [p*25 .. p*25+23]
    __shared__ float4 sq4[24];

    int bk = blockIdx.x;
    int bn = bk >> 3, kn = bk & 7;
    int b = bn >> 10;
    int t = threadIdx.x;

    int m = g_node[bn * KNODE + kn];
    const float4* row4 = (const float4*)(h + (size_t)(b * NN + m) * PD);
    if (t < 24)
        sq4[t] = ((const float4*)(h + ((size_t)bn * PP + (PP - 1)) * DD))[t];
    for (int i4 = t; i4 < PD / 4; i4 += 128) {
        int p = i4 / 24, d4 = i4 - p * 24;
        sR4[p * 25 + d4] = row4[i4];
    }
    __syncthreads();

    if (t < PP) {
        const float4* r = &sR4[t * 25];
        float a0 = 0.f, a1 = 0.f, a2 = 0.f, a3 = 0.f;
        #pragma unroll 8
        for (int j = 0; j < 24; j++) {
            float4 rv = r[j];
            float4 qv = sq4[j];
            a0 = fmaf(rv.x, qv.x, a0);
            a1 = fmaf(rv.y, qv.y, a1);
            a2 = fmaf(rv.z, qv.z, a2);
            a3 = fmaf(rv.w, qv.w, a3);
        }
        double v = (double)((a0 + a1) + (a2 + a3));
        v = v * g_inv_tok_d[bn * PP + PP - 1] * g_inv_tok_d[(b * NN + m) * PP + t];
        g_tsim[(size_t)bn * (KNODE * PP) + kn * PP + t] = (float)v;
    }
}

// =========================================================================
// K5: token select — rank-count top-12, exact dot2 re-rank, top-8 -> g_sel.
// =========================================================================
__global__ __launch_bounds__(128) void k_tsel(const float* __restrict__ h) {
    __shared__ __align__(16) float ss[KNODE * PP];
    __shared__ float sq[DD];
    __shared__ int    tcand[KTC];
    __shared__ double texd[KTC];
    __shared__ int    snode[KNODE];

    int bn = blockIdx.x;
    int b = bn >> 10;
    int t = threadIdx.x, warp = t >> 5, lane = t & 31;

    const float4* ts4 = (const float4*)(g_tsim + (size_t)bn * (KNODE * PP));
    if (t < (KNODE * PP) / 4) ((float4*)ss)[t] = ts4[t];
    if (t < DD) sq[t] = h[((size_t)bn * PP + (PP - 1)) * DD + t];
    if (t < KNODE) snode[t] = g_node[bn * KNODE + t];
    __syncthreads();

    for (int c = t; c < KNODE * PP; c += 128) {
        float vt = ss[c];
        const float4* s4 = (const float4*)ss;
        int rank = 0;
        #pragma unroll 4
        for (int j4 = 0; j4 < (KNODE * PP) / 4; j4++) {
            float4 vv = s4[j4];
            int j = j4 * 4;
            rank += (vv.x > vt || (vv.x == vt && (j + 0) < c));
            rank += (vv.y > vt || (vv.y == vt && (j + 1) < c));
            rank += (vv.z > vt || (vv.z == vt && (j + 2) < c));
            rank += (vv.w > vt || (vv.w == vt && (j + 3) < c));
        }
        if (rank < KTC) tcand[rank] = c;
    }
    __syncthreads();

    for (int cc = warp; cc < KTC; cc += 4) {
        int c = tcand[cc];
        int kn = c / PP, p = c - kn * PP;
        int m = snode[kn];
        const float* tp = h + (((size_t)(b * NN + m)) * PP + p) * (size_t)DD;
        float hi = 0.f, lo = 0.f;
        dot2_step(tp[lane],      sq[lane],      hi, lo);
        dot2_step(tp[lane + 32], sq[lane + 32], hi, lo);
        dot2_step(tp[lane + 64], sq[lane + 64], hi, lo);
        double v = (double)hi + (double)lo;
        #pragma unroll
        for (int o = 16; o; o >>= 1) v += __shfl_xor_sync(0xffffffffu, v, o);
        if (lane == 0)
            texd[cc] = v * g_inv_tok_d[bn * PP + PP - 1] *
                       g_inv_tok_d[(b * NN + m) * PP + p];
    }
    __syncthreads();

    if (t == 0) {
        unsigned used = 0;
        for (int k = 0; k < KTOK; k++) {
            int best = -1;
            for (int j = 0; j < KTC; j++) {
                if (used & (1u << j)) continue;
                if (best < 0 || texd[j] > texd[best] ||
                    (texd[j] == texd[best] && tcand[j] < tcand[best])) best = j;
            }
            used |= (1u << best);
            int c = tcand[best];
            int kn = c / PP, p = c - kn * PP;
            g_sel[bn * KTOK + k] = snode[kn] * 64 + p;
        }
    }
}

// =========================================================================
// K6: sk linear — gather 64 selected tokens/block, x @ W^T + b + nt.
// =========================================================================
__global__ __launch_bounds__(256) void k_sklin(const float* __restrict__ h,
                                               const float* __restrict__ W,
                                               const float* __restrict__ bias,
                                               const float* __restrict__ ntok,
                                               float* __restrict__ out) {
    __shared__ __align__(16) float sXT[DD * 68];
    __shared__ __align__(16) float sWT[DD * 98];
    __shared__ size_t rowoff[64];

    int r0 = blockIdx.x * 64;
    int t = threadIdx.x;

    if (t < 64) {
        int rr = r0 + t;
        int bn = rr >> 3;
        int b = bn >> 10;
        int s = g_sel[bn * KTOK + (rr & 7)];
        int m = s >> 6, p = s & 63;
        rowoff[t] = (((size_t)(b * NN + m)) * PP + p) * (size_t)DD;
    }
    __syncthreads();

    for (int i = t; i < 64 * DD; i += 256) {
        int r = i / DD, d = i - r * DD;
        sXT[d * 68 + r] = h[rowoff[r] + d];
    }
    for (int i = t; i < DD * DD; i += 256) {
        int e = i / DD, d = i - e * DD;
        sWT[d * 98 + e] = W[i];
    }
    __syncthreads();

    float nt = ntok[0];
    int tx = t & 15, ty = t >> 4;
    unsigned long long acc[4][3];
    #pragma unroll
    for (int i = 0; i < 4; i++)
        #pragma unroll
        for (int j = 0; j < 3; j++)
            acc[i][j] = pk2(bias[tx * 6 + 2 * j] + nt, bias[tx * 6 + 2 * j + 1] + nt);

    #pragma unroll 4
    for (int d = 0; d < DD; d++) {
        float4 xv = *(const float4*)(sXT + d * 68 + ty * 4);
        const unsigned long long* wp = (const unsigned long long*)(sWT + d * 98 + tx * 6);
        unsigned long long b0 = wp[0], b1 = wp[1], b2 = wp[2];
        float x[4] = {xv.x, xv.y, xv.z, xv.w};
        #pragma unroll
        for (int i = 0; i < 4; i++) {
            unsigned long long a = pk2(x[i], x[i]);
            fma2(acc[i][0], a, b0);
            fma2(acc[i][1], a, b1);
            fma2(acc[i][2], a, b2);
        }
    }

    #pragma unroll
    for (int i = 0; i < 4; i++) {
        int rr = r0 + ty * 4 + i;
        int bn = rr >> 3, k = rr & 7;
        float* orow = out + (((size_t)bn) * POUT + PP + k) * (size_t)DD + tx * 6;
        #pragma unroll
        for (int j = 0; j < 3; j++) {
            float lo, hi;
            upk2(acc[i][j], lo, hi);
            orow[2 * j] = lo;
            orow[2 * j + 1] = hi;
        }
    }
}

// =========================================================================
// K7: hf = h @ W^T + b -> out[:, :, 0:42, :].  f32x2 packed FFMA.
// =========================================================================
__global__ __launch_bounds__(256) void k_hf(const float* __restrict__ h,
                                            const float* __restrict__ W,
                                            const float* __restrict__ bias,
                                            float* __restrict__ out) {
    extern __shared__ __align__(16) float dyn[];
    float* sXT = dyn;                 // [DD][68]
    float* sWT = dyn + DD * 68;       // [DD][98]

    int r0 = blockIdx.x * 64;
    int t = threadIdx.x;

    const float* Xbase = h + (size_t)r0 * DD;
    for (int i = t; i < 64 * DD; i += 256) {
        int r = i / DD, d = i - r * DD;
        sXT[d * 68 + r] = Xbase[i];
    }
    for (int i = t; i < DD * DD; i += 256) {
        int e = i / DD, d = i - e * DD;
        sWT[d * 98 + e] = W[i];
    }
    __syncthreads();

    int tx = t & 15, ty = t >> 4;
    unsigned long long acc[4][3];
    #pragma unroll
    for (int i = 0; i < 4; i++)
        #pragma unroll
        for (int j = 0; j < 3; j++)
            acc[i][j] = pk2(bias[tx * 6 + 2 * j], bias[tx * 6 + 2 * j + 1]);

    #pragma unroll 4
    for (int d = 0; d < DD; d++) {
        float4 xv = *(const float4*)(sXT + d * 68 + ty * 4);
        const unsigned long long* wp = (const unsigned long long*)(sWT + d * 98 + tx * 6);
        unsigned long long b0 = wp[0], b1 = wp[1], b2 = wp[2];
        float x[4] = {xv.x, xv.y, xv.z, xv.w};
        #pragma unroll
        for (int i = 0; i < 4; i++) {
            unsigned long long a = pk2(x[i], x[i]);
            fma2(acc[i][0], a, b0);
            fma2(acc[i][1], a, b1);
            fma2(acc[i][2], a, b2);
        }
    }

    #pragma unroll
    for (int i = 0; i < 4; i++) {
        int r = r0 + ty * 4 + i;
        int bn = r / PP, p = r - bn * PP;
        float* orow = out + (((size_t)bn) * POUT + p) * (size_t)DD + tx * 6;
        #pragma unroll
        for (int j = 0; j < 3; j++) {
            float lo, hi;
            upk2(acc[i][j], lo, hi);
            orow[2 * j] = lo;
            orow[2 * j + 1] = hi;
        }
    }
}

// =========================================================================
extern "C" void kernel_launch(void* const* d_in, const int* in_sizes, int n_in,
                              void* d_out, int out_size) {
    const float* h    = (const float*)d_in[0];
    const float* W    = (const float*)d_in[1];
    const float* bias = (const float*)d_in[2];
    const float* ntok = (const float*)d_in[3];
    float* out = (float*)d_out;

    k_conv<<<(BB * NN * PD) / (256 * 4), 256>>>(h);                  // 1

    k_norms<<<BB * NN, 128>>>(h);                                    // 2

    size_t hf_smem = (size_t)(DD * 68 + DD * 98) * sizeof(float);
    cudaFuncSetAttribute(k_hf, cudaFuncAttributeMaxDynamicSharedMemorySize, (int)hf_smem);
    k_hf<<<(BB * NN * PP) / 64, 256, hf_smem>>>(h, W, bias, out);    // 3

    cudaFuncSetAttribute(k_sim_mma, cudaFuncAttributeMaxDynamicSharedMemorySize,
                         3 * SIM_STAGE_BYTES);
    dim3 g2(NN / 128, NN / 128, BB);
    k_sim_mma<<<g2, 256, 3 * SIM_STAGE_BYTES>>>();                   // 4  <- profiled slot

    k_topk_node<<<BB * NN, 256>>>(h);                                // 5

    k_tsim<<<BB * NN * KNODE, 128>>>(h);                             // 6

    k_tsel<<<BB * NN, 128>>>(h);                                     // 7

    k_sklin<<<(BB * NN * KTOK) / 64, 256>>>(h, W, bias, ntok, out);  // 8
}